// round 1
// baseline (speedup 1.0000x reference)
#include <cuda_runtime.h>
#include <math.h>

#define BATCH 48
#define TLEN  32
#define NCELL 528           // T*(T+1)/2
#define HSZ   512
#define NPROJ 1536          // [A | C | Sh]

// Static scratch (no allocation allowed).
__device__ __align__(16) float g_ACS[(size_t)BATCH * NCELL * NPROJ];   // ~156 MB
__device__ float g_sch[BATCH * NCELL];                                  // chart_s
__device__ __align__(16) float g_Wcat[HSZ * NPROJ];                     // [W1|W2|S], 3 MB
__device__ __align__(16) float g_ltmp[BATCH * TLEN * HSZ];              // leaf pre-norm

__host__ __device__ __forceinline__ int offs(int k) {
    return k * TLEN - (k * (k - 1)) / 2;
}

// ---------------------------------------------------------------------------
// Pack Wcat[d][j]: j<512 -> W1 = w_comp[d][j]; j<1024 -> W2 = w_comp[512+d][j-512];
// else S[d][j-1024].
// ---------------------------------------------------------------------------
__global__ void pack_wcat(const float* __restrict__ w_comp,
                          const float* __restrict__ s_bil) {
    int idx = blockIdx.x * 256 + threadIdx.x;
    int d = idx / NPROJ;
    int j = idx - d * NPROJ;
    float v;
    if (j < HSZ)            v = w_comp[d * HSZ + j];
    else if (j < 2 * HSZ)   v = w_comp[(HSZ + d) * HSZ + (j - HSZ)];
    else                    v = s_bil[d * HSZ + (j - 2 * HSZ)];
    g_Wcat[idx] = v;
}

// ---------------------------------------------------------------------------
// Leaf GEMM: (1536 x 1024) @ (1024 x 512) + bias, relu -> g_ltmp
// Tile 64x128, BK=16, 256 threads, 4x8 microtile.
// ---------------------------------------------------------------------------
__global__ void leaf_gemm(const float* __restrict__ X,
                          const float* __restrict__ W,
                          const float* __restrict__ bias) {
    __shared__ float Hs[16][68];
    __shared__ float Ws[16][128];
    int tid = threadIdx.x;
    int n0 = blockIdx.x * 128, m0 = blockIdx.y * 64;
    int ty = tid >> 4, tx = tid & 15;
    float acc[4][8];
#pragma unroll
    for (int i = 0; i < 4; i++)
#pragma unroll
        for (int j = 0; j < 8; j++) acc[i][j] = 0.f;

    int lm  = tid >> 2;         // 0..63 row in tile
    int lkq = (tid & 3) * 4;    // 0,4,8,12
    int wkk = tid >> 4;         // 0..15
    int wn  = (tid & 15) * 8;   // 0..120

    for (int k0 = 0; k0 < 1024; k0 += 16) {
        float4 hv = *(const float4*)&X[(size_t)(m0 + lm) * 1024 + k0 + lkq];
        float4 w0 = *(const float4*)&W[(size_t)(k0 + wkk) * 512 + n0 + wn];
        float4 w1 = *(const float4*)&W[(size_t)(k0 + wkk) * 512 + n0 + wn + 4];
        __syncthreads();
        Hs[lkq + 0][lm] = hv.x; Hs[lkq + 1][lm] = hv.y;
        Hs[lkq + 2][lm] = hv.z; Hs[lkq + 3][lm] = hv.w;
        *(float4*)&Ws[wkk][wn]     = w0;
        *(float4*)&Ws[wkk][wn + 4] = w1;
        __syncthreads();
#pragma unroll
        for (int kk = 0; kk < 16; kk++) {
            float av[4], bv[8];
            *(float4*)av       = *(const float4*)&Hs[kk][ty * 4];
            *(float4*)bv       = *(const float4*)&Ws[kk][tx * 8];
            *(float4*)(bv + 4) = *(const float4*)&Ws[kk][tx * 8 + 4];
#pragma unroll
            for (int i = 0; i < 4; i++)
#pragma unroll
                for (int j = 0; j < 8; j++) acc[i][j] += av[i] * bv[j];
        }
    }
#pragma unroll
    for (int i = 0; i < 4; i++) {
        int r = m0 + ty * 4 + i;
        float* o = g_ltmp + (size_t)r * 512 + n0 + tx * 8;
#pragma unroll
        for (int j = 0; j < 8; j++)
            o[j] = fmaxf(acc[i][j] + bias[n0 + tx * 8 + j], 0.f);
    }
}

// ---------------------------------------------------------------------------
// Normalize leaf rows -> chart cells (b, t), zero chart_s leaves.
// ---------------------------------------------------------------------------
__global__ void leaf_norm(float* __restrict__ chart) {
    int r = blockIdx.x;               // 0..1535
    int b = r >> 5, t = r & 31;
    int tid = threadIdx.x;            // 128
    const float4* src = (const float4*)(g_ltmp + (size_t)r * HSZ);
    float4 v = src[tid];
    float ss = v.x * v.x + v.y * v.y + v.z * v.z + v.w * v.w;
    __shared__ float red[4];
    __shared__ float s_inv;
    int w = tid >> 5, lane = tid & 31;
#pragma unroll
    for (int o = 16; o > 0; o >>= 1) ss += __shfl_xor_sync(0xffffffffu, ss, o);
    if (lane == 0) red[w] = ss;
    __syncthreads();
    if (tid == 0) {
        float tt = red[0] + red[1] + red[2] + red[3];
        s_inv = 1.f / fmaxf(sqrtf(tt), 1e-12f);
        g_sch[b * NCELL + t] = 0.f;
    }
    __syncthreads();
    float inv = s_inv;
    v.x *= inv; v.y *= inv; v.z *= inv; v.w *= inv;
    float4* dst = (float4*)(chart + ((size_t)b * NCELL + t) * HSZ);
    dst[tid] = v;
}

// ---------------------------------------------------------------------------
// Projection GEMM: for cells at [off, off+L) per batch, compute
// out[cell] = h[cell] @ Wcat  (512 -> 1536). Rows r -> (b = r/L, pos = r%L).
// Tile 64x128, BK=16, 256 threads.
// ---------------------------------------------------------------------------
__global__ void proj_kernel(const float* __restrict__ chart,
                            int off, int L, int M) {
    __shared__ float Hs[16][68];
    __shared__ float Ws[16][128];
    __shared__ int rowCell[64];
    int tid = threadIdx.x;
    int n0 = blockIdx.x * 128, m0 = blockIdx.y * 64;
    if (tid < 64) {
        int r = m0 + tid;
        rowCell[tid] = (r < M) ? ((r / L) * NCELL + off + (r % L)) : -1;
    }
    __syncthreads();
    int ty = tid >> 4, tx = tid & 15;
    float acc[4][8];
#pragma unroll
    for (int i = 0; i < 4; i++)
#pragma unroll
        for (int j = 0; j < 8; j++) acc[i][j] = 0.f;

    int lm  = tid >> 2;
    int lkq = (tid & 3) * 4;
    int wkk = tid >> 4;
    int wn  = (tid & 15) * 8;
    int myCell = rowCell[lm];

    for (int k0 = 0; k0 < HSZ; k0 += 16) {
        float4 hv = make_float4(0.f, 0.f, 0.f, 0.f);
        if (myCell >= 0)
            hv = *(const float4*)&chart[(size_t)myCell * HSZ + k0 + lkq];
        float4 w0 = *(const float4*)&g_Wcat[(size_t)(k0 + wkk) * NPROJ + n0 + wn];
        float4 w1 = *(const float4*)&g_Wcat[(size_t)(k0 + wkk) * NPROJ + n0 + wn + 4];
        __syncthreads();
        Hs[lkq + 0][lm] = hv.x; Hs[lkq + 1][lm] = hv.y;
        Hs[lkq + 2][lm] = hv.z; Hs[lkq + 3][lm] = hv.w;
        *(float4*)&Ws[wkk][wn]     = w0;
        *(float4*)&Ws[wkk][wn + 4] = w1;
        __syncthreads();
#pragma unroll
        for (int kk = 0; kk < 16; kk++) {
            float av[4], bv[8];
            *(float4*)av       = *(const float4*)&Hs[kk][ty * 4];
            *(float4*)bv       = *(const float4*)&Ws[kk][tx * 8];
            *(float4*)(bv + 4) = *(const float4*)&Ws[kk][tx * 8 + 4];
#pragma unroll
            for (int i = 0; i < 4; i++)
#pragma unroll
                for (int j = 0; j < 8; j++) acc[i][j] += av[i] * bv[j];
        }
    }
#pragma unroll
    for (int i = 0; i < 4; i++) {
        int c = rowCell[ty * 4 + i];
        if (c >= 0) {
            float* o = g_ACS + (size_t)c * NPROJ + n0 + tx * 8;
            *(float4*)o       = *(float4*)&acc[i][0];
            *(float4*)(o + 4) = *(float4*)&acc[i][4];
        }
    }
}

// ---------------------------------------------------------------------------
// Combine: one block per output cell (b, pos) at `level`.
// Pass 1 (warp-per-split): s_n = dot(Sh[l], h[r]) + s_l + s_r.
// Softmax over n on warp 0; pass 2: hbar = sum_n p_n * relu(A_l + C_r + b);
// normalize, write chart_h + chart_s.
// ---------------------------------------------------------------------------
__global__ void combine_kernel(float* __restrict__ chart,
                               const float* __restrict__ b_comp,
                               int level) {
    int L = TLEN - level;
    int cidx = blockIdx.x;
    int b = cidx / L, pos = cidx - b * L;
    int cell = b * NCELL + offs(level) + pos;

    __shared__ float sv[32];
    __shared__ float pv[32];
    __shared__ float red[8];
    __shared__ float s_inv;

    int tid = threadIdx.x, w = tid >> 5, lane = tid & 31;

    // Pass 1: score per split
    for (int n = w; n < level; n += 8) {
        int lcell = b * NCELL + offs(n) + pos;
        int rcell = b * NCELL + offs(level - 1 - n) + pos + n + 1;
        const float4* Sh4 = (const float4*)(g_ACS + (size_t)lcell * NPROJ + 2 * HSZ);
        const float4* hr4 = (const float4*)(chart + (size_t)rcell * HSZ);
        float d = 0.f;
#pragma unroll 4
        for (int i = lane; i < HSZ / 4; i += 32) {
            float4 a = Sh4[i], c4 = hr4[i];
            d += a.x * c4.x + a.y * c4.y + a.z * c4.z + a.w * c4.w;
        }
#pragma unroll
        for (int o = 16; o > 0; o >>= 1) d += __shfl_xor_sync(0xffffffffu, d, o);
        if (lane == 0) sv[n] = d + g_sch[lcell] + g_sch[rcell];
    }
    __syncthreads();

    // Softmax + sbar (warp 0, level <= 31 fits one warp)
    if (w == 0) {
        float s = (lane < level) ? sv[lane] : -1e30f;
        float m = s;
#pragma unroll
        for (int o = 16; o > 0; o >>= 1) m = fmaxf(m, __shfl_xor_sync(0xffffffffu, m, o));
        float e = (lane < level) ? expf(s - m) : 0.f;
        float se = e;
#pragma unroll
        for (int o = 16; o > 0; o >>= 1) se += __shfl_xor_sync(0xffffffffu, se, o);
        float p = e / se;
        pv[lane] = p;
        float sp = (lane < level) ? s * p : 0.f;
#pragma unroll
        for (int o = 16; o > 0; o >>= 1) sp += __shfl_xor_sync(0xffffffffu, sp, o);
        if (lane == 0) g_sch[cell] = sp;
    }
    __syncthreads();

    // Pass 2: weighted relu-sum over splits, each thread owns 2 feature dims.
    int j0 = tid, j1 = tid + 256;
    float bc0 = b_comp[j0], bc1 = b_comp[j1];
    float a0 = 0.f, a1 = 0.f;
    for (int n = 0; n < level; n++) {
        int lcell = b * NCELL + offs(n) + pos;
        int rcell = b * NCELL + offs(level - 1 - n) + pos + n + 1;
        const float* A = g_ACS + (size_t)lcell * NPROJ;
        const float* C = g_ACS + (size_t)rcell * NPROJ + HSZ;
        float p = pv[n];
        a0 += p * fmaxf(A[j0] + C[j0] + bc0, 0.f);
        a1 += p * fmaxf(A[j1] + C[j1] + bc1, 0.f);
    }

    // Normalize
    float ss = a0 * a0 + a1 * a1;
#pragma unroll
    for (int o = 16; o > 0; o >>= 1) ss += __shfl_xor_sync(0xffffffffu, ss, o);
    if (lane == 0) red[w] = ss;
    __syncthreads();
    if (tid == 0) {
        float t = 0.f;
#pragma unroll
        for (int i = 0; i < 8; i++) t += red[i];
        s_inv = 1.f / fmaxf(sqrtf(t), 1e-12f);
    }
    __syncthreads();
    float inv = s_inv;
    float* o = chart + (size_t)cell * HSZ;
    o[j0] = a0 * inv;
    o[j1] = a1 * inv;
}

// ---------------------------------------------------------------------------
extern "C" void kernel_launch(void* const* d_in, const int* in_sizes, int n_in,
                              void* d_out, int out_size) {
    const float* x      = (const float*)d_in[0];
    const float* w_leaf = (const float*)d_in[1];
    const float* b_leaf = (const float*)d_in[2];
    const float* w_comp = (const float*)d_in[3];
    const float* b_comp = (const float*)d_in[4];
    const float* s_bil  = (const float*)d_in[5];
    float* chart = (float*)d_out;

    (void)in_sizes; (void)n_in; (void)out_size;

    // Pack [W1|W2|S]
    pack_wcat<<<(HSZ * NPROJ) / 256, 256>>>(w_comp, s_bil);

    // Leaf: GEMM + relu -> normalize -> projections
    leaf_gemm<<<dim3(512 / 128, (BATCH * TLEN) / 64), 256>>>(x, w_leaf, b_leaf);
    leaf_norm<<<BATCH * TLEN, 128>>>(chart);
    {
        int M = BATCH * TLEN;
        proj_kernel<<<dim3(NPROJ / 128, (M + 63) / 64), 256>>>(chart, 0, TLEN, M);
    }

    // Levels 1..31
    for (int level = 1; level < TLEN; level++) {
        int L = TLEN - level;
        combine_kernel<<<BATCH * L, 256>>>(chart, b_comp, level);
        if (level < TLEN - 1) {                 // top level's projections never read
            int M = BATCH * L;
            proj_kernel<<<dim3(NPROJ / 128, (M + 63) / 64), 256>>>(
                chart, offs(level), L, M);
        }
    }
}

// round 3
// speedup vs baseline: 1.9073x; 1.9073x over previous
#include <cuda_runtime.h>
#include <cuda_bf16.h>
#include <math.h>
#include <cstdint>

#define BATCH 48
#define TLEN  32
#define NCELL 528           // T*(T+1)/2
#define HSZ   512
#define NPROJ 1536          // [A | C | Sh]

// ---------------------------------------------------------------------------
// Static scratch (no allocation allowed).
// ---------------------------------------------------------------------------
__device__ __align__(16) float g_ACS[(size_t)BATCH * NCELL * NPROJ];    // ~156 MB
__device__ float g_sch[BATCH * NCELL];                                   // chart_s
__device__ __align__(16) float g_ltmp[BATCH * TLEN * HSZ];               // leaf pre-norm
__device__ __align__(16) __nv_bfloat16 g_WT_hi[(size_t)NPROJ * HSZ];     // WcatT hi
__device__ __align__(16) __nv_bfloat16 g_WT_lo[(size_t)NPROJ * HSZ];     // WcatT lo
__device__ __align__(16) __nv_bfloat16 g_chh[(size_t)BATCH * NCELL * HSZ]; // chart hi
__device__ __align__(16) __nv_bfloat16 g_chl[(size_t)BATCH * NCELL * HSZ]; // chart lo

__host__ __device__ __forceinline__ int offs(int k) {
    return k * TLEN - (k * (k - 1)) / 2;
}

__device__ __forceinline__ uint32_t smem_to_u32(const void* p) {
    uint32_t a;
    asm("{ .reg .u64 t; cvta.to.shared.u64 t, %1; cvt.u32.u64 %0, t; }"
        : "=r"(a) : "l"(p));
    return a;
}
template <int N> __device__ __forceinline__ void cp_wait() {
    asm volatile("cp.async.wait_group %0;" :: "n"(N) : "memory");
}
__device__ __forceinline__ void cp_commit() {
    asm volatile("cp.async.commit_group;" ::: "memory");
}
__device__ __forceinline__ void cp16(uint32_t dst, const void* src, uint32_t srcsz) {
    asm volatile("cp.async.cg.shared.global [%0], [%1], 16, %2;"
                 :: "r"(dst), "l"(src), "r"(srcsz) : "memory");
}
__device__ __forceinline__ void ldm4(uint32_t* r, uint32_t addr) {
    asm volatile("ldmatrix.sync.aligned.m8n8.x4.shared.b16 {%0,%1,%2,%3}, [%4];"
                 : "=r"(r[0]), "=r"(r[1]), "=r"(r[2]), "=r"(r[3]) : "r"(addr));
}
__device__ __forceinline__ void mma16816(float* c, const uint32_t* a,
                                         uint32_t b0, uint32_t b1) {
    asm volatile(
        "mma.sync.aligned.m16n8k16.row.col.f32.bf16.bf16.f32 "
        "{%0,%1,%2,%3}, {%4,%5,%6,%7}, {%8,%9}, {%0,%1,%2,%3};"
        : "+f"(c[0]), "+f"(c[1]), "+f"(c[2]), "+f"(c[3])
        : "r"(a[0]), "r"(a[1]), "r"(a[2]), "r"(a[3]), "r"(b0), "r"(b1));
}

// ---------------------------------------------------------------------------
// Pack transposed concat weight [W1|W2|S] into bf16 hi/lo, N-major (K contig).
// WT[j][k] = Wcat[k][j].
// ---------------------------------------------------------------------------
__global__ void pack_wt(const float* __restrict__ w_comp,
                        const float* __restrict__ s_bil) {
    int idx = blockIdx.x * 256 + threadIdx.x;   // NPROJ*HSZ total
    int j = idx >> 9;
    int k = idx & 511;
    float v;
    if (j < HSZ)            v = w_comp[k * HSZ + j];
    else if (j < 2 * HSZ)   v = w_comp[(HSZ + k) * HSZ + (j - HSZ)];
    else                    v = s_bil[k * HSZ + (j - 2 * HSZ)];
    __nv_bfloat16 hi = __float2bfloat16(v);
    float lo = v - __bfloat162float(hi);
    g_WT_hi[idx] = hi;
    g_WT_lo[idx] = __float2bfloat16(lo);
}

// ---------------------------------------------------------------------------
// Leaf GEMM: (1536 x 1024) @ (1024 x 512) + bias, relu -> g_ltmp (fp32 SIMT)
// ---------------------------------------------------------------------------
__global__ void leaf_gemm(const float* __restrict__ X,
                          const float* __restrict__ W,
                          const float* __restrict__ bias) {
    __shared__ float Hs[16][68];
    __shared__ float Ws[16][128];
    int tid = threadIdx.x;
    int n0 = blockIdx.x * 128, m0 = blockIdx.y * 64;
    int ty = tid >> 4, tx = tid & 15;
    float acc[4][8];
#pragma unroll
    for (int i = 0; i < 4; i++)
#pragma unroll
        for (int j = 0; j < 8; j++) acc[i][j] = 0.f;

    int lm  = tid >> 2;
    int lkq = (tid & 3) * 4;
    int wkk = tid >> 4;
    int wn  = (tid & 15) * 8;

    for (int k0 = 0; k0 < 1024; k0 += 16) {
        float4 hv = *(const float4*)&X[(size_t)(m0 + lm) * 1024 + k0 + lkq];
        float4 w0 = *(const float4*)&W[(size_t)(k0 + wkk) * 512 + n0 + wn];
        float4 w1 = *(const float4*)&W[(size_t)(k0 + wkk) * 512 + n0 + wn + 4];
        __syncthreads();
        Hs[lkq + 0][lm] = hv.x; Hs[lkq + 1][lm] = hv.y;
        Hs[lkq + 2][lm] = hv.z; Hs[lkq + 3][lm] = hv.w;
        *(float4*)&Ws[wkk][wn]     = w0;
        *(float4*)&Ws[wkk][wn + 4] = w1;
        __syncthreads();
#pragma unroll
        for (int kk = 0; kk < 16; kk++) {
            float av[4], bv[8];
            *(float4*)av       = *(const float4*)&Hs[kk][ty * 4];
            *(float4*)bv       = *(const float4*)&Ws[kk][tx * 8];
            *(float4*)(bv + 4) = *(const float4*)&Ws[kk][tx * 8 + 4];
#pragma unroll
            for (int i = 0; i < 4; i++)
#pragma unroll
                for (int j = 0; j < 8; j++) acc[i][j] += av[i] * bv[j];
        }
    }
#pragma unroll
    for (int i = 0; i < 4; i++) {
        int r = m0 + ty * 4 + i;
        float* o = g_ltmp + (size_t)r * 512 + n0 + tx * 8;
#pragma unroll
        for (int j = 0; j < 8; j++)
            o[j] = fmaxf(acc[i][j] + bias[n0 + tx * 8 + j], 0.f);
    }
}

// ---------------------------------------------------------------------------
// Normalize leaf rows -> chart cells (b, t) fp32 + bf16 hi/lo; zero leaf scores.
// ---------------------------------------------------------------------------
__global__ void leaf_norm(float* __restrict__ chart) {
    int r = blockIdx.x;
    int b = r >> 5, t = r & 31;
    int tid = threadIdx.x;            // 128
    const float4* src = (const float4*)(g_ltmp + (size_t)r * HSZ);
    float4 v = src[tid];
    float ss = v.x * v.x + v.y * v.y + v.z * v.z + v.w * v.w;
    __shared__ float red[4];
    __shared__ float s_inv;
    int w = tid >> 5, lane = tid & 31;
#pragma unroll
    for (int o = 16; o > 0; o >>= 1) ss += __shfl_xor_sync(0xffffffffu, ss, o);
    if (lane == 0) red[w] = ss;
    __syncthreads();
    if (tid == 0) {
        float tt = red[0] + red[1] + red[2] + red[3];
        s_inv = 1.f / fmaxf(sqrtf(tt), 1e-12f);
        g_sch[b * NCELL + t] = 0.f;
    }
    __syncthreads();
    float inv = s_inv;
    v.x *= inv; v.y *= inv; v.z *= inv; v.w *= inv;
    size_t base = ((size_t)b * NCELL + t) * HSZ;
    *(float4*)(chart + base + tid * 4) = v;
    float f[4] = {v.x, v.y, v.z, v.w};
    __align__(8) __nv_bfloat16 hi[4], lo[4];
#pragma unroll
    for (int i = 0; i < 4; i++) {
        hi[i] = __float2bfloat16(f[i]);
        lo[i] = __float2bfloat16(f[i] - __bfloat162float(hi[i]));
    }
    *(uint2*)(g_chh + base + tid * 4) = *(const uint2*)hi;
    *(uint2*)(g_chl + base + tid * 4) = *(const uint2*)lo;
}

// ---------------------------------------------------------------------------
// Tensor-core projection via mma.sync bf16 (3x split): out = h @ Wcat.
// CTA: 128(M) x 128(N), 256 thr (8 warps, 2x4), warp tile 64x32.
// BK=32, double-buffered cp.async. A from g_chh/g_chl, B from g_WT_hi/lo.
// smem row stride: 40 bf16 (80 B).
// ---------------------------------------------------------------------------
#define PSTRIDE 40
#define PMAT    (128 * PSTRIDE * 2)      // 10240 B per matrix
#define PSTAGE  (4 * PMAT)               // 40960 B per stage

__global__ __launch_bounds__(256, 1)
void proj_mma(int off, int L, int M) {
    extern __shared__ __align__(16) char dsm[];
    uint32_t sbase = smem_to_u32(dsm);
    __shared__ int rowCell[128];

    int tid = threadIdx.x, wid = tid >> 5, lane = tid & 31;
    int n0 = blockIdx.x * 128;
    int m0 = blockIdx.y * 128;
    if (tid < 128) {
        int r = m0 + tid;
        rowCell[tid] = (r < M) ? ((r / L) * NCELL + off + (r % L)) : -1;
    }
    __syncthreads();

    // cp.async issue for one stage: 2048 16B chunks, 8 per thread.
    auto issue = [&](int s) {
        int buf = s & 1;
        int kc  = s * 32;
        uint32_t stage = sbase + buf * PSTAGE;
#pragma unroll
        for (int i = 0; i < 8; i++) {
            int c   = tid + i * 256;
            int mat = i >> 1;
            int r   = c & 511;
            int row = r >> 2;
            int q   = r & 3;
            uint32_t dst = stage + mat * PMAT + row * (PSTRIDE * 2) + q * 16;
            if (mat < 2) {
                int cell = rowCell[row];
                const __nv_bfloat16* sp = (mat == 0 ? g_chh : g_chl);
                const void* src = sp + ((size_t)(cell < 0 ? 0 : cell) * HSZ + kc + q * 8);
                cp16(dst, src, cell < 0 ? 0u : 16u);
            } else {
                const __nv_bfloat16* sp = (mat == 2 ? g_WT_hi : g_WT_lo);
                cp16(dst, sp + ((size_t)(n0 + row) * HSZ + kc + q * 8), 16u);
            }
        }
        cp_commit();
    };

    float acc[4][4][4];
#pragma unroll
    for (int mi = 0; mi < 4; mi++)
#pragma unroll
        for (int ni = 0; ni < 4; ni++)
#pragma unroll
            for (int q = 0; q < 4; q++) acc[mi][ni][q] = 0.f;

    int wm = wid & 1, wn = wid >> 1;
    int laneRow = lane & 15;
    int laneK8  = (lane >> 4) * 8;
    uint32_t aRowOff = (uint32_t)(wm * 64 + laneRow) * (PSTRIDE * 2) + laneK8 * 2;
    uint32_t bRowOff = (uint32_t)(wn * 32 + laneRow) * (PSTRIDE * 2) + laneK8 * 2;

    issue(0);
    for (int kt = 0; kt < 16; kt++) {
        if (kt + 1 < 16) { issue(kt + 1); cp_wait<1>(); }
        else             { cp_wait<0>(); }
        __syncthreads();
        uint32_t stage = sbase + (kt & 1) * PSTAGE;
#pragma unroll
        for (int kh = 0; kh < 2; kh++) {
            uint32_t kb = kh * 32;   // 16 bf16 = 32 bytes
            uint32_t ahi[4][4], alo[4][4], bhi[2][4], blo[2][4];
#pragma unroll
            for (int mi = 0; mi < 4; mi++) {
                uint32_t ao = mi * 16 * (PSTRIDE * 2) + kb;
                ldm4(ahi[mi], stage + 0 * PMAT + aRowOff + ao);
                ldm4(alo[mi], stage + 1 * PMAT + aRowOff + ao);
            }
#pragma unroll
            for (int nj = 0; nj < 2; nj++) {
                uint32_t bo = nj * 16 * (PSTRIDE * 2) + kb;
                ldm4(bhi[nj], stage + 2 * PMAT + bRowOff + bo);
                ldm4(blo[nj], stage + 3 * PMAT + bRowOff + bo);
            }
#pragma unroll
            for (int mi = 0; mi < 4; mi++) {
#pragma unroll
                for (int ni = 0; ni < 4; ni++) {
                    int nj = ni >> 1, sel = ni & 1;
                    uint32_t bh0 = bhi[nj][sel], bh1 = bhi[nj][sel + 2];
                    uint32_t bl0 = blo[nj][sel], bl1 = blo[nj][sel + 2];
                    mma16816(acc[mi][ni], ahi[mi], bh0, bh1);
                    mma16816(acc[mi][ni], ahi[mi], bl0, bl1);
                    mma16816(acc[mi][ni], alo[mi], bh0, bh1);
                }
            }
        }
        __syncthreads();
    }

    // Epilogue: c0,c1 -> (row, col..col+1); c2,c3 -> (row+8, ...)
    int qrow = lane >> 2, qcol = (lane & 3) * 2;
#pragma unroll
    for (int mi = 0; mi < 4; mi++) {
        int r0 = wm * 64 + mi * 16 + qrow;
        int c0 = rowCell[r0];
        int c1 = rowCell[r0 + 8];
#pragma unroll
        for (int ni = 0; ni < 4; ni++) {
            int col = n0 + wn * 32 + ni * 8 + qcol;
            if (c0 >= 0)
                *(float2*)(g_ACS + (size_t)c0 * NPROJ + col) =
                    make_float2(acc[mi][ni][0], acc[mi][ni][1]);
            if (c1 >= 0)
                *(float2*)(g_ACS + (size_t)c1 * NPROJ + col) =
                    make_float2(acc[mi][ni][2], acc[mi][ni][3]);
        }
    }
}

// ---------------------------------------------------------------------------
// Combine: one block per output cell (b, pos) at `level`.
// ---------------------------------------------------------------------------
__global__ void combine_kernel(float* __restrict__ chart,
                               const float* __restrict__ b_comp,
                               int level) {
    int L = TLEN - level;
    int cidx = blockIdx.x;
    int b = cidx / L, pos = cidx - b * L;
    int cell = b * NCELL + offs(level) + pos;

    __shared__ float sv[32];
    __shared__ float pv[32];
    __shared__ float red[8];
    __shared__ float s_inv;

    int tid = threadIdx.x, w = tid >> 5, lane = tid & 31;

    // Pass 1: score per split
    for (int n = w; n < level; n += 8) {
        int lcell = b * NCELL + offs(n) + pos;
        int rcell = b * NCELL + offs(level - 1 - n) + pos + n + 1;
        const float4* Sh4 = (const float4*)(g_ACS + (size_t)lcell * NPROJ + 2 * HSZ);
        const float4* hr4 = (const float4*)(chart + (size_t)rcell * HSZ);
        float d = 0.f;
#pragma unroll 4
        for (int i = lane; i < HSZ / 4; i += 32) {
            float4 a = Sh4[i], c4 = hr4[i];
            d += a.x * c4.x + a.y * c4.y + a.z * c4.z + a.w * c4.w;
        }
#pragma unroll
        for (int o = 16; o > 0; o >>= 1) d += __shfl_xor_sync(0xffffffffu, d, o);
        if (lane == 0) sv[n] = d + g_sch[lcell] + g_sch[rcell];
    }
    __syncthreads();

    // Softmax + sbar (warp 0)
    if (w == 0) {
        float s = (lane < level) ? sv[lane] : -1e30f;
        float m = s;
#pragma unroll
        for (int o = 16; o > 0; o >>= 1) m = fmaxf(m, __shfl_xor_sync(0xffffffffu, m, o));
        float e = (lane < level) ? expf(s - m) : 0.f;
        float se = e;
#pragma unroll
        for (int o = 16; o > 0; o >>= 1) se += __shfl_xor_sync(0xffffffffu, se, o);
        float p = e / se;
        pv[lane] = p;
        float sp = (lane < level) ? s * p : 0.f;
#pragma unroll
        for (int o = 16; o > 0; o >>= 1) sp += __shfl_xor_sync(0xffffffffu, sp, o);
        if (lane == 0) g_sch[cell] = sp;
    }
    __syncthreads();

    // Pass 2: weighted relu-sum over splits
    int j0 = tid, j1 = tid + 256;
    float bc0 = b_comp[j0], bc1 = b_comp[j1];
    float a0 = 0.f, a1 = 0.f;
    for (int n = 0; n < level; n++) {
        int lcell = b * NCELL + offs(n) + pos;
        int rcell = b * NCELL + offs(level - 1 - n) + pos + n + 1;
        const float* A = g_ACS + (size_t)lcell * NPROJ;
        const float* C = g_ACS + (size_t)rcell * NPROJ + HSZ;
        float p = pv[n];
        a0 += p * fmaxf(A[j0] + C[j0] + bc0, 0.f);
        a1 += p * fmaxf(A[j1] + C[j1] + bc1, 0.f);
    }

    // Normalize
    float ss = a0 * a0 + a1 * a1;
#pragma unroll
    for (int o = 16; o > 0; o >>= 1) ss += __shfl_xor_sync(0xffffffffu, ss, o);
    if (lane == 0) red[w] = ss;
    __syncthreads();
    if (tid == 0) {
        float t = 0.f;
#pragma unroll
        for (int i = 0; i < 8; i++) t += red[i];
        s_inv = 1.f / fmaxf(sqrtf(t), 1e-12f);
    }
    __syncthreads();
    float inv = s_inv;
    float v0 = a0 * inv, v1 = a1 * inv;
    size_t base = (size_t)cell * HSZ;
    chart[base + j0] = v0;
    chart[base + j1] = v1;
    __nv_bfloat16 h0 = __float2bfloat16(v0);
    __nv_bfloat16 h1 = __float2bfloat16(v1);
    g_chh[base + j0] = h0;
    g_chh[base + j1] = h1;
    g_chl[base + j0] = __float2bfloat16(v0 - __bfloat162float(h0));
    g_chl[base + j1] = __float2bfloat16(v1 - __bfloat162float(h1));
}

// ---------------------------------------------------------------------------
extern "C" void kernel_launch(void* const* d_in, const int* in_sizes, int n_in,
                              void* d_out, int out_size) {
    const float* x      = (const float*)d_in[0];
    const float* w_leaf = (const float*)d_in[1];
    const float* b_leaf = (const float*)d_in[2];
    const float* w_comp = (const float*)d_in[3];
    const float* b_comp = (const float*)d_in[4];
    const float* s_bil  = (const float*)d_in[5];
    float* chart = (float*)d_out;

    (void)in_sizes; (void)n_in; (void)out_size;

    const int DSMEM = 2 * PSTAGE;   // 81920 B
    cudaFuncSetAttribute(proj_mma, cudaFuncAttributeMaxDynamicSharedMemorySize, DSMEM);

    pack_wt<<<(NPROJ * HSZ) / 256, 256>>>(w_comp, s_bil);
    leaf_gemm<<<dim3(512 / 128, (BATCH * TLEN) / 64), 256>>>(x, w_leaf, b_leaf);
    leaf_norm<<<BATCH * TLEN, 128>>>(chart);
    proj_mma<<<dim3(NPROJ / 128, (BATCH * TLEN + 127) / 128), 256, DSMEM>>>(
        0, TLEN, BATCH * TLEN);

    for (int level = 1; level < TLEN; level++) {
        int L = TLEN - level;
        combine_kernel<<<BATCH * L, 256>>>(chart, b_comp, level);
        if (level < TLEN - 1) {
            int M = BATCH * L;
            proj_mma<<<dim3(NPROJ / 128, (M + 127) / 128), 256, DSMEM>>>(
                offs(level), L, M);
        }
    }
}

// round 4
// speedup vs baseline: 2.2427x; 1.1759x over previous
#include <cuda_runtime.h>
#include <cuda_bf16.h>
#include <math.h>
#include <cstdint>

#define BATCH 48
#define TLEN  32
#define NCELL 528           // T*(T+1)/2
#define HSZ   512
#define NPROJ 1536          // [A | C | Sh]

// ---------------------------------------------------------------------------
// Static scratch (no allocation allowed).
// ---------------------------------------------------------------------------
__device__ __align__(16) float g_ACS[(size_t)BATCH * NCELL * NPROJ];    // ~156 MB
__device__ float g_sch[BATCH * NCELL];                                   // chart_s
__device__ __align__(16) float g_ltmp[BATCH * TLEN * HSZ];               // leaf pre-norm
__device__ __align__(16) __nv_bfloat16 g_WT_hi[(size_t)NPROJ * HSZ];     // WcatT hi
__device__ __align__(16) __nv_bfloat16 g_WT_lo[(size_t)NPROJ * HSZ];     // WcatT lo
__device__ __align__(16) __nv_bfloat16 g_chh[(size_t)BATCH * NCELL * HSZ]; // chart hi
__device__ __align__(16) __nv_bfloat16 g_chl[(size_t)BATCH * NCELL * HSZ]; // chart lo

__host__ __device__ __forceinline__ int offs(int k) {
    return k * TLEN - (k * (k - 1)) / 2;
}

__device__ __forceinline__ uint32_t smem_to_u32(const void* p) {
    uint32_t a;
    asm("{ .reg .u64 t; cvta.to.shared.u64 t, %1; cvt.u32.u64 %0, t; }"
        : "=r"(a) : "l"(p));
    return a;
}
template <int N> __device__ __forceinline__ void cp_wait() {
    asm volatile("cp.async.wait_group %0;" :: "n"(N) : "memory");
}
__device__ __forceinline__ void cp_commit() {
    asm volatile("cp.async.commit_group;" ::: "memory");
}
__device__ __forceinline__ void cp16(uint32_t dst, const void* src, uint32_t srcsz) {
    asm volatile("cp.async.cg.shared.global [%0], [%1], 16, %2;"
                 :: "r"(dst), "l"(src), "r"(srcsz) : "memory");
}
__device__ __forceinline__ void ldm4(uint32_t* r, uint32_t addr) {
    asm volatile("ldmatrix.sync.aligned.m8n8.x4.shared.b16 {%0,%1,%2,%3}, [%4];"
                 : "=r"(r[0]), "=r"(r[1]), "=r"(r[2]), "=r"(r[3]) : "r"(addr));
}
__device__ __forceinline__ void mma16816(float* c, const uint32_t* a,
                                         uint32_t b0, uint32_t b1) {
    asm volatile(
        "mma.sync.aligned.m16n8k16.row.col.f32.bf16.bf16.f32 "
        "{%0,%1,%2,%3}, {%4,%5,%6,%7}, {%8,%9}, {%0,%1,%2,%3};"
        : "+f"(c[0]), "+f"(c[1]), "+f"(c[2]), "+f"(c[3])
        : "r"(a[0]), "r"(a[1]), "r"(a[2]), "r"(a[3]), "r"(b0), "r"(b1));
}

// ---------------------------------------------------------------------------
// Pack transposed concat weight [W1|W2|S] into bf16 hi/lo, N-major (K contig).
// ---------------------------------------------------------------------------
__global__ void pack_wt(const float* __restrict__ w_comp,
                        const float* __restrict__ s_bil) {
    int idx = blockIdx.x * 256 + threadIdx.x;   // NPROJ*HSZ total
    int j = idx >> 9;
    int k = idx & 511;
    float v;
    if (j < HSZ)            v = w_comp[k * HSZ + j];
    else if (j < 2 * HSZ)   v = w_comp[(HSZ + k) * HSZ + (j - HSZ)];
    else                    v = s_bil[k * HSZ + (j - 2 * HSZ)];
    __nv_bfloat16 hi = __float2bfloat16(v);
    float lo = v - __bfloat162float(hi);
    g_WT_hi[idx] = hi;
    g_WT_lo[idx] = __float2bfloat16(lo);
}

// ---------------------------------------------------------------------------
// Leaf GEMM: (1536 x 1024) @ (1024 x 512) + bias, relu -> g_ltmp (fp32 SIMT)
// ---------------------------------------------------------------------------
__global__ void leaf_gemm(const float* __restrict__ X,
                          const float* __restrict__ W,
                          const float* __restrict__ bias) {
    __shared__ float Hs[16][68];
    __shared__ float Ws[16][128];
    int tid = threadIdx.x;
    int n0 = blockIdx.x * 128, m0 = blockIdx.y * 64;
    int ty = tid >> 4, tx = tid & 15;
    float acc[4][8];
#pragma unroll
    for (int i = 0; i < 4; i++)
#pragma unroll
        for (int j = 0; j < 8; j++) acc[i][j] = 0.f;

    int lm  = tid >> 2;
    int lkq = (tid & 3) * 4;
    int wkk = tid >> 4;
    int wn  = (tid & 15) * 8;

    for (int k0 = 0; k0 < 1024; k0 += 16) {
        float4 hv = *(const float4*)&X[(size_t)(m0 + lm) * 1024 + k0 + lkq];
        float4 w0 = *(const float4*)&W[(size_t)(k0 + wkk) * 512 + n0 + wn];
        float4 w1 = *(const float4*)&W[(size_t)(k0 + wkk) * 512 + n0 + wn + 4];
        __syncthreads();
        Hs[lkq + 0][lm] = hv.x; Hs[lkq + 1][lm] = hv.y;
        Hs[lkq + 2][lm] = hv.z; Hs[lkq + 3][lm] = hv.w;
        *(float4*)&Ws[wkk][wn]     = w0;
        *(float4*)&Ws[wkk][wn + 4] = w1;
        __syncthreads();
#pragma unroll
        for (int kk = 0; kk < 16; kk++) {
            float av[4], bv[8];
            *(float4*)av       = *(const float4*)&Hs[kk][ty * 4];
            *(float4*)bv       = *(const float4*)&Ws[kk][tx * 8];
            *(float4*)(bv + 4) = *(const float4*)&Ws[kk][tx * 8 + 4];
#pragma unroll
            for (int i = 0; i < 4; i++)
#pragma unroll
                for (int j = 0; j < 8; j++) acc[i][j] += av[i] * bv[j];
        }
    }
#pragma unroll
    for (int i = 0; i < 4; i++) {
        int r = m0 + ty * 4 + i;
        float* o = g_ltmp + (size_t)r * 512 + n0 + tx * 8;
#pragma unroll
        for (int j = 0; j < 8; j++)
            o[j] = fmaxf(acc[i][j] + bias[n0 + tx * 8 + j], 0.f);
    }
}

// ---------------------------------------------------------------------------
// Normalize leaf rows -> chart cells (b, t) fp32 + bf16 hi/lo; zero leaf scores.
// ---------------------------------------------------------------------------
__global__ void leaf_norm(float* __restrict__ chart) {
    int r = blockIdx.x;
    int b = r >> 5, t = r & 31;
    int tid = threadIdx.x;            // 128
    const float4* src = (const float4*)(g_ltmp + (size_t)r * HSZ);
    float4 v = src[tid];
    float ss = v.x * v.x + v.y * v.y + v.z * v.z + v.w * v.w;
    __shared__ float red[4];
    __shared__ float s_inv;
    int w = tid >> 5, lane = tid & 31;
#pragma unroll
    for (int o = 16; o > 0; o >>= 1) ss += __shfl_xor_sync(0xffffffffu, ss, o);
    if (lane == 0) red[w] = ss;
    __syncthreads();
    if (tid == 0) {
        float tt = red[0] + red[1] + red[2] + red[3];
        s_inv = 1.f / fmaxf(sqrtf(tt), 1e-12f);
        g_sch[b * NCELL + t] = 0.f;
    }
    __syncthreads();
    float inv = s_inv;
    v.x *= inv; v.y *= inv; v.z *= inv; v.w *= inv;
    size_t base = ((size_t)b * NCELL + t) * HSZ;
    *(float4*)(chart + base + tid * 4) = v;
    float f[4] = {v.x, v.y, v.z, v.w};
    __align__(8) __nv_bfloat16 hi[4], lo[4];
#pragma unroll
    for (int i = 0; i < 4; i++) {
        hi[i] = __float2bfloat16(f[i]);
        lo[i] = __float2bfloat16(f[i] - __bfloat162float(hi[i]));
    }
    *(uint2*)(g_chh + base + tid * 4) = *(const uint2*)hi;
    *(uint2*)(g_chl + base + tid * 4) = *(const uint2*)lo;
}

// ---------------------------------------------------------------------------
// Projection via mma.sync bf16 (3x split): out = h @ Wcat.
// CTA tile: 128(M) x 64(N), 8 warps (4x2), warp tile 32x32. BK=32, 2-stage
// cp.async. smem 60KB -> 2 CTA/SM. Row stride 40 bf16 (80B), conflict-free.
// ---------------------------------------------------------------------------
#define PROWB   80                       // bytes per smem row (32 bf16 + pad)
#define PAMAT   (128 * PROWB)            // 10240
#define PBMAT   (64 * PROWB)             // 5120
#define POFF_AH 0
#define POFF_AL (PAMAT)
#define POFF_BH (2 * PAMAT)
#define POFF_BL (2 * PAMAT + PBMAT)
#define PSTAGE  (2 * PAMAT + 2 * PBMAT)  // 30720

__global__ __launch_bounds__(256, 2)
void proj_mma(int off, int L, int M) {
    extern __shared__ __align__(16) char dsm[];
    uint32_t sbase = smem_to_u32(dsm);
    __shared__ int rowCell[128];

    int tid = threadIdx.x, wid = tid >> 5, lane = tid & 31;
    int n0 = blockIdx.x * 64;
    int m0 = blockIdx.y * 128;
    if (tid < 128) {
        int r = m0 + tid;
        rowCell[tid] = (r < M) ? ((r / L) * NCELL + off + (r % L)) : -1;
    }
    __syncthreads();

    // One stage: A hi/lo 1024 chunks + B hi/lo 512 chunks, 6 per thread.
    auto issue = [&](int s) {
        uint32_t stage = sbase + (s & 1) * PSTAGE;
        int kc = s * 32;
#pragma unroll
        for (int i = 0; i < 4; i++) {                     // A
            int r = tid + (i & 1) * 256;
            int row = r >> 2, q = r & 3;
            uint32_t dst = stage + ((i >> 1) ? POFF_AL : POFF_AH)
                         + row * PROWB + q * 16;
            int cell = rowCell[row];
            const __nv_bfloat16* sp = ((i >> 1) == 0 ? g_chh : g_chl);
            const void* src = sp + ((size_t)(cell < 0 ? 0 : cell) * HSZ + kc + q * 8);
            cp16(dst, src, cell < 0 ? 0u : 16u);
        }
        {                                                  // B hi
            int row = tid >> 2, q = tid & 3;
            cp16(stage + POFF_BH + row * PROWB + q * 16,
                 g_WT_hi + ((size_t)(n0 + row) * HSZ + kc + q * 8), 16u);
            cp16(stage + POFF_BL + row * PROWB + q * 16,
                 g_WT_lo + ((size_t)(n0 + row) * HSZ + kc + q * 8), 16u);
        }
        cp_commit();
    };

    float acc[2][4][4];
#pragma unroll
    for (int mi = 0; mi < 2; mi++)
#pragma unroll
        for (int ni = 0; ni < 4; ni++)
#pragma unroll
            for (int q = 0; q < 4; q++) acc[mi][ni][q] = 0.f;

    int wm = wid & 3, wn = wid >> 2;        // 4 x 2 warp grid
    int laneRow = lane & 15;
    uint32_t lk = (uint32_t)(lane >> 4) * 16;
    uint32_t aRowOff = (uint32_t)(wm * 32 + laneRow) * PROWB + lk;
    uint32_t bRowOff = (uint32_t)(wn * 32 + laneRow) * PROWB + lk;

    issue(0);
    for (int kt = 0; kt < 16; kt++) {
        if (kt + 1 < 16) { issue(kt + 1); cp_wait<1>(); }
        else             { cp_wait<0>(); }
        __syncthreads();
        uint32_t stage = sbase + (kt & 1) * PSTAGE;
#pragma unroll
        for (int kh = 0; kh < 2; kh++) {
            uint32_t kb = kh * 32;
            uint32_t ahi[2][4], alo[2][4], bhi[2][4], blo[2][4];
#pragma unroll
            for (int mi = 0; mi < 2; mi++) {
                uint32_t ao = mi * 16 * PROWB + kb;
                ldm4(ahi[mi], stage + POFF_AH + aRowOff + ao);
                ldm4(alo[mi], stage + POFF_AL + aRowOff + ao);
            }
#pragma unroll
            for (int nj = 0; nj < 2; nj++) {
                uint32_t bo = nj * 16 * PROWB + kb;
                ldm4(bhi[nj], stage + POFF_BH + bRowOff + bo);
                ldm4(blo[nj], stage + POFF_BL + bRowOff + bo);
            }
#pragma unroll
            for (int mi = 0; mi < 2; mi++) {
#pragma unroll
                for (int ni = 0; ni < 4; ni++) {
                    int nj = ni >> 1, sel = ni & 1;
                    uint32_t bh0 = bhi[nj][sel], bh1 = bhi[nj][sel + 2];
                    uint32_t bl0 = blo[nj][sel], bl1 = blo[nj][sel + 2];
                    mma16816(acc[mi][ni], ahi[mi], bh0, bh1);
                    mma16816(acc[mi][ni], ahi[mi], bl0, bl1);
                    mma16816(acc[mi][ni], alo[mi], bh0, bh1);
                }
            }
        }
        __syncthreads();
    }

    int qrow = lane >> 2, qcol = (lane & 3) * 2;
#pragma unroll
    for (int mi = 0; mi < 2; mi++) {
        int r0 = wm * 32 + mi * 16 + qrow;
        int c0 = rowCell[r0];
        int c1 = rowCell[r0 + 8];
#pragma unroll
        for (int ni = 0; ni < 4; ni++) {
            int col = n0 + wn * 32 + ni * 8 + qcol;
            if (c0 >= 0)
                *(float2*)(g_ACS + (size_t)c0 * NPROJ + col) =
                    make_float2(acc[mi][ni][0], acc[mi][ni][1]);
            if (c1 >= 0)
                *(float2*)(g_ACS + (size_t)c1 * NPROJ + col) =
                    make_float2(acc[mi][ni][2], acc[mi][ni][3]);
        }
    }
}

// ---------------------------------------------------------------------------
// Combine: one block per output cell (b, pos) at `level`.
// ---------------------------------------------------------------------------
__global__ __launch_bounds__(256)
void combine_kernel(float* __restrict__ chart,
                    const float* __restrict__ b_comp,
                    int level) {
    int L = TLEN - level;
    int cidx = blockIdx.x;
    int b = cidx / L, pos = cidx - b * L;
    int cell = b * NCELL + offs(level) + pos;

    __shared__ float sv[32];
    __shared__ float pv[32];
    __shared__ float red[8];
    __shared__ float s_inv;

    int tid = threadIdx.x, w = tid >> 5, lane = tid & 31;

    // Pass 1: score per split (one warp per split, strided)
    for (int n = w; n < level; n += 8) {
        int lcell = b * NCELL + offs(n) + pos;
        int rcell = b * NCELL + offs(level - 1 - n) + pos + n + 1;
        const float4* Sh4 = (const float4*)(g_ACS + (size_t)lcell * NPROJ + 2 * HSZ);
        const float4* hr4 = (const float4*)(chart + (size_t)rcell * HSZ);
        float d = 0.f;
#pragma unroll 4
        for (int i = lane; i < HSZ / 4; i += 32) {
            float4 a = __ldg(Sh4 + i), c4 = __ldg(hr4 + i);
            d += a.x * c4.x + a.y * c4.y + a.z * c4.z + a.w * c4.w;
        }
#pragma unroll
        for (int o = 16; o > 0; o >>= 1) d += __shfl_xor_sync(0xffffffffu, d, o);
        if (lane == 0) sv[n] = d + g_sch[lcell] + g_sch[rcell];
    }
    __syncthreads();

    // Softmax + sbar (warp 0)
    if (w == 0) {
        float s = (lane < level) ? sv[lane] : -1e30f;
        float m = s;
#pragma unroll
        for (int o = 16; o > 0; o >>= 1) m = fmaxf(m, __shfl_xor_sync(0xffffffffu, m, o));
        float e = (lane < level) ? expf(s - m) : 0.f;
        float se = e;
#pragma unroll
        for (int o = 16; o > 0; o >>= 1) se += __shfl_xor_sync(0xffffffffu, se, o);
        float p = e / se;
        pv[lane] = p;
        float sp = (lane < level) ? s * p : 0.f;
#pragma unroll
        for (int o = 16; o > 0; o >>= 1) sp += __shfl_xor_sync(0xffffffffu, sp, o);
        if (lane == 0) g_sch[cell] = sp;
    }
    __syncthreads();

    // Pass 2: weighted relu-sum; each thread owns float2 at j = 2*tid.
    int j = tid * 2;
    const float2 bc = *(const float2*)&b_comp[j];
    float ax = 0.f, ay = 0.f;
    int base0 = b * NCELL + pos;
#pragma unroll 2
    for (int n = 0; n < level; n++) {
        int lcell = base0 + offs(n);
        int rcell = base0 + offs(level - 1 - n) + n + 1;
        float2 A = __ldg((const float2*)(g_ACS + (size_t)lcell * NPROJ + j));
        float2 C = __ldg((const float2*)(g_ACS + (size_t)rcell * NPROJ + HSZ + j));
        float p = pv[n];
        ax += p * fmaxf(A.x + C.x + bc.x, 0.f);
        ay += p * fmaxf(A.y + C.y + bc.y, 0.f);
    }

    // Normalize
    float ss = ax * ax + ay * ay;
#pragma unroll
    for (int o = 16; o > 0; o >>= 1) ss += __shfl_xor_sync(0xffffffffu, ss, o);
    if (lane == 0) red[w] = ss;
    __syncthreads();
    if (tid == 0) {
        float t = 0.f;
#pragma unroll
        for (int i = 0; i < 8; i++) t += red[i];
        s_inv = 1.f / fmaxf(sqrtf(t), 1e-12f);
    }
    __syncthreads();
    float inv = s_inv;
    float v0 = ax * inv, v1 = ay * inv;
    size_t base = (size_t)cell * HSZ;
    *(float2*)(chart + base + j) = make_float2(v0, v1);
    __nv_bfloat16 h0 = __float2bfloat16(v0);
    __nv_bfloat16 h1 = __float2bfloat16(v1);
    __align__(4) __nv_bfloat16 hv[2] = {h0, h1};
    __align__(4) __nv_bfloat16 lv[2] = {
        __float2bfloat16(v0 - __bfloat162float(h0)),
        __float2bfloat16(v1 - __bfloat162float(h1))};
    *(uint32_t*)(g_chh + base + j) = *(const uint32_t*)hv;
    *(uint32_t*)(g_chl + base + j) = *(const uint32_t*)lv;
}

// ---------------------------------------------------------------------------
extern "C" void kernel_launch(void* const* d_in, const int* in_sizes, int n_in,
                              void* d_out, int out_size) {
    const float* x      = (const float*)d_in[0];
    const float* w_leaf = (const float*)d_in[1];
    const float* b_leaf = (const float*)d_in[2];
    const float* w_comp = (const float*)d_in[3];
    const float* b_comp = (const float*)d_in[4];
    const float* s_bil  = (const float*)d_in[5];
    float* chart = (float*)d_out;

    (void)in_sizes; (void)n_in; (void)out_size;

    const int DSMEM = 2 * PSTAGE;   // 61440 B
    cudaFuncSetAttribute(proj_mma, cudaFuncAttributeMaxDynamicSharedMemorySize, DSMEM);

    pack_wt<<<(NPROJ * HSZ) / 256, 256>>>(w_comp, s_bil);
    leaf_gemm<<<dim3(512 / 128, (BATCH * TLEN) / 64), 256>>>(x, w_leaf, b_leaf);
    leaf_norm<<<BATCH * TLEN, 128>>>(chart);
    proj_mma<<<dim3(NPROJ / 64, (BATCH * TLEN + 127) / 128), 256, DSMEM>>>(
        0, TLEN, BATCH * TLEN);

    for (int level = 1; level < TLEN; level++) {
        int L = TLEN - level;
        combine_kernel<<<BATCH * L, 256>>>(chart, b_comp, level);
        if (level < TLEN - 1) {
            int M = BATCH * L;
            proj_mma<<<dim3(NPROJ / 64, (M + 127) / 128), 256, DSMEM>>>(
                offs(level), L, M);
        }
    }
}

// round 5
// speedup vs baseline: 2.3631x; 1.0537x over previous
#include <cuda_runtime.h>
#include <cuda_bf16.h>
#include <math.h>
#include <cstdint>

#define BATCH 48
#define TLEN  32
#define NCELL 528           // T*(T+1)/2
#define HSZ   512
#define NPROJ 1536          // [A | C | Sh]

// ---------------------------------------------------------------------------
// Static scratch (no allocation allowed).
// ---------------------------------------------------------------------------
__device__ __align__(16) float g_ACS[(size_t)BATCH * NCELL * NPROJ];    // ~156 MB
__device__ float g_sch[BATCH * NCELL];                                   // chart_s
__device__ __align__(16) float g_ltmp[BATCH * TLEN * HSZ];               // leaf pre-norm
__device__ __align__(16) __nv_bfloat16 g_WT_hi[(size_t)NPROJ * HSZ];     // WcatT hi
__device__ __align__(16) __nv_bfloat16 g_WT_lo[(size_t)NPROJ * HSZ];     // WcatT lo
__device__ __align__(16) __nv_bfloat16 g_chh[(size_t)BATCH * NCELL * HSZ]; // chart hi
__device__ __align__(16) __nv_bfloat16 g_chl[(size_t)BATCH * NCELL * HSZ]; // chart lo
__device__ __align__(16) __nv_bfloat16 g_Xh[(size_t)BATCH * TLEN * 1024];  // x hi
__device__ __align__(16) __nv_bfloat16 g_Xl[(size_t)BATCH * TLEN * 1024];  // x lo
__device__ __align__(16) __nv_bfloat16 g_WLh[(size_t)HSZ * 1024];          // w_leafT hi
__device__ __align__(16) __nv_bfloat16 g_WLl[(size_t)HSZ * 1024];          // w_leafT lo

__host__ __device__ __forceinline__ int offs(int k) {
    return k * TLEN - (k * (k - 1)) / 2;
}

__device__ __forceinline__ uint32_t smem_to_u32(const void* p) {
    uint32_t a;
    asm("{ .reg .u64 t; cvta.to.shared.u64 t, %1; cvt.u32.u64 %0, t; }"
        : "=r"(a) : "l"(p));
    return a;
}
template <int N> __device__ __forceinline__ void cp_wait() {
    asm volatile("cp.async.wait_group %0;" :: "n"(N) : "memory");
}
__device__ __forceinline__ void cp_commit() {
    asm volatile("cp.async.commit_group;" ::: "memory");
}
__device__ __forceinline__ void cp16(uint32_t dst, const void* src, uint32_t srcsz) {
    asm volatile("cp.async.cg.shared.global [%0], [%1], 16, %2;"
                 :: "r"(dst), "l"(src), "r"(srcsz) : "memory");
}
__device__ __forceinline__ void ldm4(uint32_t* r, uint32_t addr) {
    asm volatile("ldmatrix.sync.aligned.m8n8.x4.shared.b16 {%0,%1,%2,%3}, [%4];"
                 : "=r"(r[0]), "=r"(r[1]), "=r"(r[2]), "=r"(r[3]) : "r"(addr));
}
__device__ __forceinline__ void mma16816(float* c, const uint32_t* a,
                                         uint32_t b0, uint32_t b1) {
    asm volatile(
        "mma.sync.aligned.m16n8k16.row.col.f32.bf16.bf16.f32 "
        "{%0,%1,%2,%3}, {%4,%5,%6,%7}, {%8,%9}, {%0,%1,%2,%3};"
        : "+f"(c[0]), "+f"(c[1]), "+f"(c[2]), "+f"(c[3])
        : "r"(a[0]), "r"(a[1]), "r"(a[2]), "r"(a[3]), "r"(b0), "r"(b1));
}

// ---------------------------------------------------------------------------
// Pack kernels: fp32 -> bf16 hi/lo
// ---------------------------------------------------------------------------
__global__ void pack_wt(const float* __restrict__ w_comp,
                        const float* __restrict__ s_bil) {
    int idx = blockIdx.x * 256 + threadIdx.x;   // NPROJ*HSZ
    int j = idx >> 9;
    int k = idx & 511;
    float v;
    if (j < HSZ)            v = w_comp[k * HSZ + j];
    else if (j < 2 * HSZ)   v = w_comp[(HSZ + k) * HSZ + (j - HSZ)];
    else                    v = s_bil[k * HSZ + (j - 2 * HSZ)];
    __nv_bfloat16 hi = __float2bfloat16(v);
    g_WT_hi[idx] = hi;
    g_WT_lo[idx] = __float2bfloat16(v - __bfloat162float(hi));
}

__global__ void pack_x(const float* __restrict__ x) {
    int idx = blockIdx.x * 256 + threadIdx.x;   // 1536*1024
    float v = x[idx];
    __nv_bfloat16 hi = __float2bfloat16(v);
    g_Xh[idx] = hi;
    g_Xl[idx] = __float2bfloat16(v - __bfloat162float(hi));
}

__global__ void pack_wl(const float* __restrict__ w_leaf) {
    int idx = blockIdx.x * 256 + threadIdx.x;   // 512*1024
    int n = idx >> 10;
    int k = idx & 1023;
    float v = w_leaf[k * HSZ + n];
    __nv_bfloat16 hi = __float2bfloat16(v);
    g_WLh[idx] = hi;
    g_WLl[idx] = __float2bfloat16(v - __bfloat162float(hi));
}

// ---------------------------------------------------------------------------
// Shared GEMM tile constants: CTA 128(M) x 64(N), 8 warps (4x2), warp 32x32,
// BK=32, 3-stage cp.async pipeline. smem row stride 80B (conflict-free).
// ---------------------------------------------------------------------------
#define PROWB   80
#define PAMAT   (128 * PROWB)            // 10240
#define PBMAT   (64 * PROWB)             // 5120
#define POFF_AH 0
#define POFF_AL (PAMAT)
#define POFF_BH (2 * PAMAT)
#define POFF_BL (2 * PAMAT + PBMAT)
#define PSTAGE  (2 * PAMAT + 2 * PBMAT)  // 30720
#define NSTAGE  3
#define DSMEM   (NSTAGE * PSTAGE)        // 92160

// Compute one BK=32 chunk from smem stage into acc (3x bf16 split).
__device__ __forceinline__ void gemm_chunk(uint32_t stage, uint32_t aRowOff,
                                           uint32_t bRowOff, float acc[2][4][4]) {
#pragma unroll
    for (int kh = 0; kh < 2; kh++) {
        uint32_t kb = kh * 32;
        uint32_t ahi[2][4], alo[2][4], bhi[2][4], blo[2][4];
#pragma unroll
        for (int mi = 0; mi < 2; mi++) {
            uint32_t ao = mi * 16 * PROWB + kb;
            ldm4(ahi[mi], stage + POFF_AH + aRowOff + ao);
            ldm4(alo[mi], stage + POFF_AL + aRowOff + ao);
        }
#pragma unroll
        for (int nj = 0; nj < 2; nj++) {
            uint32_t bo = nj * 16 * PROWB + kb;
            ldm4(bhi[nj], stage + POFF_BH + bRowOff + bo);
            ldm4(blo[nj], stage + POFF_BL + bRowOff + bo);
        }
#pragma unroll
        for (int mi = 0; mi < 2; mi++) {
#pragma unroll
            for (int ni = 0; ni < 4; ni++) {
                int nj = ni >> 1, sel = ni & 1;
                uint32_t bh0 = bhi[nj][sel], bh1 = bhi[nj][sel + 2];
                uint32_t bl0 = blo[nj][sel], bl1 = blo[nj][sel + 2];
                mma16816(acc[mi][ni], ahi[mi], bh0, bh1);
                mma16816(acc[mi][ni], ahi[mi], bl0, bl1);
                mma16816(acc[mi][ni], alo[mi], bh0, bh1);
            }
        }
    }
}

// ---------------------------------------------------------------------------
// Projection: out[cell] = h[cell] @ Wcat (512 -> 1536), gathered rows.
// ---------------------------------------------------------------------------
__global__ __launch_bounds__(256, 2)
void proj_mma(int off, int L, int M) {
    extern __shared__ __align__(16) char dsm[];
    uint32_t sbase = smem_to_u32(dsm);
    __shared__ int rowCell[128];

    int tid = threadIdx.x, wid = tid >> 5, lane = tid & 31;
    int n0 = blockIdx.x * 64;
    int m0 = blockIdx.y * 128;
    if (tid < 128) {
        int r = m0 + tid;
        rowCell[tid] = (r < M) ? ((r / L) * NCELL + off + (r % L)) : -1;
    }
    __syncthreads();

    auto issue = [&](int s) {
        uint32_t stage = sbase + (s % NSTAGE) * PSTAGE;
        int kc = s * 32;
#pragma unroll
        for (int i = 0; i < 4; i++) {                     // A hi/lo
            int r = tid + (i & 1) * 256;
            int row = r >> 2, q = r & 3;
            uint32_t dst = stage + ((i >> 1) ? POFF_AL : POFF_AH)
                         + row * PROWB + q * 16;
            int cell = rowCell[row];
            const __nv_bfloat16* sp = ((i >> 1) == 0 ? g_chh : g_chl);
            const void* src = sp + ((size_t)(cell < 0 ? 0 : cell) * HSZ + kc + q * 8);
            cp16(dst, src, cell < 0 ? 0u : 16u);
        }
        {                                                  // B hi/lo
            int row = tid >> 2, q = tid & 3;
            cp16(stage + POFF_BH + row * PROWB + q * 16,
                 g_WT_hi + ((size_t)(n0 + row) * HSZ + kc + q * 8), 16u);
            cp16(stage + POFF_BL + row * PROWB + q * 16,
                 g_WT_lo + ((size_t)(n0 + row) * HSZ + kc + q * 8), 16u);
        }
        cp_commit();
    };

    float acc[2][4][4];
#pragma unroll
    for (int mi = 0; mi < 2; mi++)
#pragma unroll
        for (int ni = 0; ni < 4; ni++)
#pragma unroll
            for (int q = 0; q < 4; q++) acc[mi][ni][q] = 0.f;

    int wm = wid & 3, wn = wid >> 2;
    int laneRow = lane & 15;
    uint32_t lk = (uint32_t)(lane >> 4) * 16;
    uint32_t aRowOff = (uint32_t)(wm * 32 + laneRow) * PROWB + lk;
    uint32_t bRowOff = (uint32_t)(wn * 32 + laneRow) * PROWB + lk;

    const int KITER = 16;
    issue(0); issue(1);
    for (int kt = 0; kt < KITER; kt++) {
        if (kt + 1 < KITER) cp_wait<1>(); else cp_wait<0>();
        __syncthreads();
        if (kt + 2 < KITER) issue(kt + 2);
        gemm_chunk(sbase + (kt % NSTAGE) * PSTAGE, aRowOff, bRowOff, acc);
    }

    int qrow = lane >> 2, qcol = (lane & 3) * 2;
#pragma unroll
    for (int mi = 0; mi < 2; mi++) {
        int r0 = wm * 32 + mi * 16 + qrow;
        int c0 = rowCell[r0];
        int c1 = rowCell[r0 + 8];
#pragma unroll
        for (int ni = 0; ni < 4; ni++) {
            int col = n0 + wn * 32 + ni * 8 + qcol;
            if (c0 >= 0)
                *(float2*)(g_ACS + (size_t)c0 * NPROJ + col) =
                    make_float2(acc[mi][ni][0], acc[mi][ni][1]);
            if (c1 >= 0)
                *(float2*)(g_ACS + (size_t)c1 * NPROJ + col) =
                    make_float2(acc[mi][ni][2], acc[mi][ni][3]);
        }
    }
}

// ---------------------------------------------------------------------------
// Leaf GEMM via mma: g_ltmp = relu(x @ w_leaf + b). M=1536, N=512, K=1024.
// ---------------------------------------------------------------------------
__global__ __launch_bounds__(256, 2)
void leaf_mma(const float* __restrict__ bias) {
    extern __shared__ __align__(16) char dsm[];
    uint32_t sbase = smem_to_u32(dsm);
    int tid = threadIdx.x, wid = tid >> 5, lane = tid & 31;
    int n0 = blockIdx.x * 64;     // 8
    int m0 = blockIdx.y * 128;    // 12

    auto issue = [&](int s) {
        uint32_t stage = sbase + (s % NSTAGE) * PSTAGE;
        int kc = s * 32;
#pragma unroll
        for (int i = 0; i < 4; i++) {
            int r = tid + (i & 1) * 256;
            int row = r >> 2, q = r & 3;
            uint32_t dst = stage + ((i >> 1) ? POFF_AL : POFF_AH)
                         + row * PROWB + q * 16;
            const __nv_bfloat16* sp = ((i >> 1) == 0 ? g_Xh : g_Xl);
            cp16(dst, sp + ((size_t)(m0 + row) * 1024 + kc + q * 8), 16u);
        }
        {
            int row = tid >> 2, q = tid & 3;
            cp16(stage + POFF_BH + row * PROWB + q * 16,
                 g_WLh + ((size_t)(n0 + row) * 1024 + kc + q * 8), 16u);
            cp16(stage + POFF_BL + row * PROWB + q * 16,
                 g_WLl + ((size_t)(n0 + row) * 1024 + kc + q * 8), 16u);
        }
        cp_commit();
    };

    float acc[2][4][4];
#pragma unroll
    for (int mi = 0; mi < 2; mi++)
#pragma unroll
        for (int ni = 0; ni < 4; ni++)
#pragma unroll
            for (int q = 0; q < 4; q++) acc[mi][ni][q] = 0.f;

    int wm = wid & 3, wn = wid >> 2;
    int laneRow = lane & 15;
    uint32_t lk = (uint32_t)(lane >> 4) * 16;
    uint32_t aRowOff = (uint32_t)(wm * 32 + laneRow) * PROWB + lk;
    uint32_t bRowOff = (uint32_t)(wn * 32 + laneRow) * PROWB + lk;

    const int KITER = 32;
    issue(0); issue(1);
    for (int kt = 0; kt < KITER; kt++) {
        if (kt + 1 < KITER) cp_wait<1>(); else cp_wait<0>();
        __syncthreads();
        if (kt + 2 < KITER) issue(kt + 2);
        gemm_chunk(sbase + (kt % NSTAGE) * PSTAGE, aRowOff, bRowOff, acc);
    }

    int qrow = lane >> 2, qcol = (lane & 3) * 2;
#pragma unroll
    for (int mi = 0; mi < 2; mi++) {
        int r0 = m0 + wm * 32 + mi * 16 + qrow;
#pragma unroll
        for (int ni = 0; ni < 4; ni++) {
            int col = n0 + wn * 32 + ni * 8 + qcol;
            float2 bc = *(const float2*)&bias[col];
            *(float2*)(g_ltmp + (size_t)r0 * HSZ + col) =
                make_float2(fmaxf(acc[mi][ni][0] + bc.x, 0.f),
                            fmaxf(acc[mi][ni][1] + bc.y, 0.f));
            *(float2*)(g_ltmp + (size_t)(r0 + 8) * HSZ + col) =
                make_float2(fmaxf(acc[mi][ni][2] + bc.x, 0.f),
                            fmaxf(acc[mi][ni][3] + bc.y, 0.f));
        }
    }
}

// ---------------------------------------------------------------------------
// Normalize leaf rows -> chart cells (b, t) fp32 + bf16 hi/lo; zero leaf scores.
// ---------------------------------------------------------------------------
__global__ void leaf_norm(float* __restrict__ chart) {
    int r = blockIdx.x;
    int b = r >> 5, t = r & 31;
    int tid = threadIdx.x;            // 128
    const float4* src = (const float4*)(g_ltmp + (size_t)r * HSZ);
    float4 v = src[tid];
    float ss = v.x * v.x + v.y * v.y + v.z * v.z + v.w * v.w;
    __shared__ float red[4];
    __shared__ float s_inv;
    int w = tid >> 5, lane = tid & 31;
#pragma unroll
    for (int o = 16; o > 0; o >>= 1) ss += __shfl_xor_sync(0xffffffffu, ss, o);
    if (lane == 0) red[w] = ss;
    __syncthreads();
    if (tid == 0) {
        float tt = red[0] + red[1] + red[2] + red[3];
        s_inv = 1.f / fmaxf(sqrtf(tt), 1e-12f);
        g_sch[b * NCELL + t] = 0.f;
    }
    __syncthreads();
    float inv = s_inv;
    v.x *= inv; v.y *= inv; v.z *= inv; v.w *= inv;
    size_t base = ((size_t)b * NCELL + t) * HSZ;
    *(float4*)(chart + base + tid * 4) = v;
    float f[4] = {v.x, v.y, v.z, v.w};
    __align__(8) __nv_bfloat16 hi[4], lo[4];
#pragma unroll
    for (int i = 0; i < 4; i++) {
        hi[i] = __float2bfloat16(f[i]);
        lo[i] = __float2bfloat16(f[i] - __bfloat162float(hi[i]));
    }
    *(uint2*)(g_chh + base + tid * 4) = *(const uint2*)hi;
    *(uint2*)(g_chl + base + tid * 4) = *(const uint2*)lo;
}

// ---------------------------------------------------------------------------
// Combine: one block per output cell (b, pos) at `level`.
// ---------------------------------------------------------------------------
__global__ __launch_bounds__(256)
void combine_kernel(float* __restrict__ chart,
                    const float* __restrict__ b_comp,
                    int level) {
    int L = TLEN - level;
    int cidx = blockIdx.x;
    int b = cidx / L, pos = cidx - b * L;
    int cell = b * NCELL + offs(level) + pos;

    __shared__ float sv[32];
    __shared__ float pv[32];
    __shared__ float red[8];
    __shared__ float s_inv;

    int tid = threadIdx.x, w = tid >> 5, lane = tid & 31;

    // Pass 1: score per split (one warp per split, strided)
    for (int n = w; n < level; n += 8) {
        int lcell = b * NCELL + offs(n) + pos;
        int rcell = b * NCELL + offs(level - 1 - n) + pos + n + 1;
        const float4* Sh4 = (const float4*)(g_ACS + (size_t)lcell * NPROJ + 2 * HSZ);
        const float4* hr4 = (const float4*)(chart + (size_t)rcell * HSZ);
        float d = 0.f;
#pragma unroll 4
        for (int i = lane; i < HSZ / 4; i += 32) {
            float4 a = __ldg(Sh4 + i), c4 = __ldg(hr4 + i);
            d += a.x * c4.x + a.y * c4.y + a.z * c4.z + a.w * c4.w;
        }
#pragma unroll
        for (int o = 16; o > 0; o >>= 1) d += __shfl_xor_sync(0xffffffffu, d, o);
        if (lane == 0) sv[n] = d + g_sch[lcell] + g_sch[rcell];
    }
    __syncthreads();

    // Softmax + sbar (warp 0)
    if (w == 0) {
        float s = (lane < level) ? sv[lane] : -1e30f;
        float m = s;
#pragma unroll
        for (int o = 16; o > 0; o >>= 1) m = fmaxf(m, __shfl_xor_sync(0xffffffffu, m, o));
        float e = (lane < level) ? expf(s - m) : 0.f;
        float se = e;
#pragma unroll
        for (int o = 16; o > 0; o >>= 1) se += __shfl_xor_sync(0xffffffffu, se, o);
        float p = e / se;
        pv[lane] = p;
        float sp = (lane < level) ? s * p : 0.f;
#pragma unroll
        for (int o = 16; o > 0; o >>= 1) sp += __shfl_xor_sync(0xffffffffu, sp, o);
        if (lane == 0) g_sch[cell] = sp;
    }
    __syncthreads();

    // Pass 2: weighted relu-sum; each thread owns float2 at j = 2*tid.
    int j = tid * 2;
    const float2 bc = *(const float2*)&b_comp[j];
    float ax = 0.f, ay = 0.f;
    int base0 = b * NCELL + pos;
#pragma unroll 2
    for (int n = 0; n < level; n++) {
        int lcell = base0 + offs(n);
        int rcell = base0 + offs(level - 1 - n) + n + 1;
        float2 A = __ldg((const float2*)(g_ACS + (size_t)lcell * NPROJ + j));
        float2 C = __ldg((const float2*)(g_ACS + (size_t)rcell * NPROJ + HSZ + j));
        float p = pv[n];
        ax += p * fmaxf(A.x + C.x + bc.x, 0.f);
        ay += p * fmaxf(A.y + C.y + bc.y, 0.f);
    }

    // Normalize
    float ss = ax * ax + ay * ay;
#pragma unroll
    for (int o = 16; o > 0; o >>= 1) ss += __shfl_xor_sync(0xffffffffu, ss, o);
    if (lane == 0) red[w] = ss;
    __syncthreads();
    if (tid == 0) {
        float t = 0.f;
#pragma unroll
        for (int i = 0; i < 8; i++) t += red[i];
        s_inv = 1.f / fmaxf(sqrtf(t), 1e-12f);
    }
    __syncthreads();
    float inv = s_inv;
    float v0 = ax * inv, v1 = ay * inv;
    size_t base = (size_t)cell * HSZ;
    *(float2*)(chart + base + j) = make_float2(v0, v1);
    __nv_bfloat16 h0 = __float2bfloat16(v0);
    __nv_bfloat16 h1 = __float2bfloat16(v1);
    __align__(4) __nv_bfloat16 hv[2] = {h0, h1};
    __align__(4) __nv_bfloat16 lv[2] = {
        __float2bfloat16(v0 - __bfloat162float(h0)),
        __float2bfloat16(v1 - __bfloat162float(h1))};
    *(uint32_t*)(g_chh + base + j) = *(const uint32_t*)hv;
    *(uint32_t*)(g_chl + base + j) = *(const uint32_t*)lv;
}

// ---------------------------------------------------------------------------
extern "C" void kernel_launch(void* const* d_in, const int* in_sizes, int n_in,
                              void* d_out, int out_size) {
    const float* x      = (const float*)d_in[0];
    const float* w_leaf = (const float*)d_in[1];
    const float* b_leaf = (const float*)d_in[2];
    const float* w_comp = (const float*)d_in[3];
    const float* b_comp = (const float*)d_in[4];
    const float* s_bil  = (const float*)d_in[5];
    float* chart = (float*)d_out;

    (void)in_sizes; (void)n_in; (void)out_size;

    cudaFuncSetAttribute(proj_mma, cudaFuncAttributeMaxDynamicSharedMemorySize, DSMEM);
    cudaFuncSetAttribute(leaf_mma, cudaFuncAttributeMaxDynamicSharedMemorySize, DSMEM);

    pack_wt<<<(NPROJ * HSZ) / 256, 256>>>(w_comp, s_bil);
    pack_x<<<(BATCH * TLEN * 1024) / 256, 256>>>(x);
    pack_wl<<<(HSZ * 1024) / 256, 256>>>(w_leaf);

    leaf_mma<<<dim3(HSZ / 64, (BATCH * TLEN) / 128), 256, DSMEM>>>(b_leaf);
    leaf_norm<<<BATCH * TLEN, 128>>>(chart);
    proj_mma<<<dim3(NPROJ / 64, (BATCH * TLEN + 127) / 128), 256, DSMEM>>>(
        0, TLEN, BATCH * TLEN);

    for (int level = 1; level < TLEN; level++) {
        int L = TLEN - level;
        combine_kernel<<<BATCH * L, 256>>>(chart, b_comp, level);
        if (level < TLEN - 1) {
            int M = BATCH * L;
            proj_mma<<<dim3(NPROJ / 64, (M + 127) / 128), 256, DSMEM>>>(
                offs(level), L, M);
        }
    }
}

// round 6
// speedup vs baseline: 2.4372x; 1.0314x over previous
#include <cuda_runtime.h>
#include <cuda_bf16.h>
#include <math.h>
#include <cstdint>

#define BATCH 48
#define TLEN  32
#define NCELL 528           // T*(T+1)/2
#define HSZ   512
#define NPROJ 1536          // [A | C | Sh]

// ---------------------------------------------------------------------------
// Static scratch (no allocation allowed).
// ---------------------------------------------------------------------------
__device__ __align__(16) float g_ACS[(size_t)BATCH * NCELL * NPROJ];    // ~156 MB
__device__ float g_sch[BATCH * NCELL];                                   // chart_s
__device__ __align__(16) float g_ltmp[BATCH * TLEN * HSZ];               // leaf pre-norm
__device__ __align__(16) __nv_bfloat16 g_WT_hi[(size_t)NPROJ * HSZ];     // WcatT hi
__device__ __align__(16) __nv_bfloat16 g_WT_lo[(size_t)NPROJ * HSZ];     // WcatT lo
__device__ __align__(16) __nv_bfloat16 g_chh[(size_t)BATCH * NCELL * HSZ]; // chart hi
__device__ __align__(16) __nv_bfloat16 g_chl[(size_t)BATCH * NCELL * HSZ]; // chart lo
__device__ __align__(16) __nv_bfloat16 g_Xh[(size_t)BATCH * TLEN * 1024];  // x hi
__device__ __align__(16) __nv_bfloat16 g_Xl[(size_t)BATCH * TLEN * 1024];  // x lo
__device__ __align__(16) __nv_bfloat16 g_WLh[(size_t)HSZ * 1024];          // w_leafT hi
__device__ __align__(16) __nv_bfloat16 g_WLl[(size_t)HSZ * 1024];          // w_leafT lo

__host__ __device__ __forceinline__ int offs(int k) {
    return k * TLEN - (k * (k - 1)) / 2;
}

__device__ __forceinline__ uint32_t smem_to_u32(const void* p) {
    uint32_t a;
    asm("{ .reg .u64 t; cvta.to.shared.u64 t, %1; cvt.u32.u64 %0, t; }"
        : "=r"(a) : "l"(p));
    return a;
}
template <int N> __device__ __forceinline__ void cp_wait() {
    asm volatile("cp.async.wait_group %0;" :: "n"(N) : "memory");
}
__device__ __forceinline__ void cp_commit() {
    asm volatile("cp.async.commit_group;" ::: "memory");
}
__device__ __forceinline__ void cp16(uint32_t dst, const void* src, uint32_t srcsz) {
    asm volatile("cp.async.cg.shared.global [%0], [%1], 16, %2;"
                 :: "r"(dst), "l"(src), "r"(srcsz) : "memory");
}
__device__ __forceinline__ void ldm4(uint32_t* r, uint32_t addr) {
    asm volatile("ldmatrix.sync.aligned.m8n8.x4.shared.b16 {%0,%1,%2,%3}, [%4];"
                 : "=r"(r[0]), "=r"(r[1]), "=r"(r[2]), "=r"(r[3]) : "r"(addr));
}
__device__ __forceinline__ void mma16816(float* c, const uint32_t* a,
                                         uint32_t b0, uint32_t b1) {
    asm volatile(
        "mma.sync.aligned.m16n8k16.row.col.f32.bf16.bf16.f32 "
        "{%0,%1,%2,%3}, {%4,%5,%6,%7}, {%8,%9}, {%0,%1,%2,%3};"
        : "+f"(c[0]), "+f"(c[1]), "+f"(c[2]), "+f"(c[3])
        : "r"(a[0]), "r"(a[1]), "r"(a[2]), "r"(a[3]), "r"(b0), "r"(b1));
}

// ---------------------------------------------------------------------------
// Pack kernels: fp32 -> bf16 hi/lo
// ---------------------------------------------------------------------------
__global__ void pack_wt(const float* __restrict__ w_comp,
                        const float* __restrict__ s_bil) {
    int idx = blockIdx.x * 256 + threadIdx.x;   // NPROJ*HSZ
    int j = idx >> 9;
    int k = idx & 511;
    float v;
    if (j < HSZ)            v = w_comp[k * HSZ + j];
    else if (j < 2 * HSZ)   v = w_comp[(HSZ + k) * HSZ + (j - HSZ)];
    else                    v = s_bil[k * HSZ + (j - 2 * HSZ)];
    __nv_bfloat16 hi = __float2bfloat16(v);
    g_WT_hi[idx] = hi;
    g_WT_lo[idx] = __float2bfloat16(v - __bfloat162float(hi));
}

__global__ void pack_x(const float* __restrict__ x) {
    int idx = blockIdx.x * 256 + threadIdx.x;   // 1536*1024
    float v = x[idx];
    __nv_bfloat16 hi = __float2bfloat16(v);
    g_Xh[idx] = hi;
    g_Xl[idx] = __float2bfloat16(v - __bfloat162float(hi));
}

__global__ void pack_wl(const float* __restrict__ w_leaf) {
    int idx = blockIdx.x * 256 + threadIdx.x;   // 512*1024
    int n = idx >> 10;
    int k = idx & 1023;
    float v = w_leaf[k * HSZ + n];
    __nv_bfloat16 hi = __float2bfloat16(v);
    g_WLh[idx] = hi;
    g_WLl[idx] = __float2bfloat16(v - __bfloat162float(hi));
}

// ---------------------------------------------------------------------------
// GEMM tiling: CTA 64(M) x 64(N), 128 threads (4 warps, 2x2), warp 32x32,
// BK=32, 3-stage cp.async. smem row stride 80B. 60KB total -> 3 CTAs/SM.
// ---------------------------------------------------------------------------
#define PROWB   80
#define PHALF   (64 * PROWB)             // 5120 per operand half
#define POFF_AH 0
#define POFF_AL (PHALF)
#define POFF_BH (2 * PHALF)
#define POFF_BL (3 * PHALF)
#define PSTAGE  (4 * PHALF)              // 20480
#define NSTAGE  3
#define DSMEM   (NSTAGE * PSTAGE)        // 61440

// Compute one BK=32 chunk from smem stage into acc (3x bf16 split).
__device__ __forceinline__ void gemm_chunk(uint32_t stage, uint32_t aRowOff,
                                           uint32_t bRowOff, float acc[2][4][4]) {
#pragma unroll
    for (int kh = 0; kh < 2; kh++) {
        uint32_t kb = kh * 32;
        uint32_t ahi[2][4], alo[2][4], bhi[2][4], blo[2][4];
#pragma unroll
        for (int mi = 0; mi < 2; mi++) {
            uint32_t ao = mi * 16 * PROWB + kb;
            ldm4(ahi[mi], stage + POFF_AH + aRowOff + ao);
            ldm4(alo[mi], stage + POFF_AL + aRowOff + ao);
        }
#pragma unroll
        for (int nj = 0; nj < 2; nj++) {
            uint32_t bo = nj * 16 * PROWB + kb;
            ldm4(bhi[nj], stage + POFF_BH + bRowOff + bo);
            ldm4(blo[nj], stage + POFF_BL + bRowOff + bo);
        }
#pragma unroll
        for (int mi = 0; mi < 2; mi++) {
#pragma unroll
            for (int ni = 0; ni < 4; ni++) {
                int nj = ni >> 1, sel = ni & 1;
                uint32_t bh0 = bhi[nj][sel], bh1 = bhi[nj][sel + 2];
                uint32_t bl0 = blo[nj][sel], bl1 = blo[nj][sel + 2];
                mma16816(acc[mi][ni], ahi[mi], bh0, bh1);
                mma16816(acc[mi][ni], ahi[mi], bl0, bl1);
                mma16816(acc[mi][ni], alo[mi], bh0, bh1);
            }
        }
    }
}

// ---------------------------------------------------------------------------
// Projection: out[cell] = h[cell] @ Wcat (512 -> 1536), gathered rows.
// ---------------------------------------------------------------------------
__global__ __launch_bounds__(128, 3)
void proj_mma(int off, int L, int M) {
    extern __shared__ __align__(16) char dsm[];
    uint32_t sbase = smem_to_u32(dsm);
    __shared__ int rowCell[64];

    int tid = threadIdx.x, wid = tid >> 5, lane = tid & 31;
    int n0 = blockIdx.x * 64;
    int m0 = blockIdx.y * 64;
    if (tid < 64) {
        int r = m0 + tid;
        rowCell[tid] = (r < M) ? ((r / L) * NCELL + off + (r % L)) : -1;
    }
    __syncthreads();

    auto issue = [&](int s) {
        uint32_t stage = sbase + (s % NSTAGE) * PSTAGE;
        int kc = s * 32;
#pragma unroll
        for (int i = 0; i < 4; i++) {                     // A hi/lo: 512 chunks
            int c = tid + i * 128;
            int half = c >> 8;
            int rr = c & 255;
            int row = rr >> 2, q = rr & 3;
            uint32_t dst = stage + (half ? POFF_AL : POFF_AH) + row * PROWB + q * 16;
            int cell = rowCell[row];
            const __nv_bfloat16* sp = (half ? g_chl : g_chh);
            const void* src = sp + ((size_t)(cell < 0 ? 0 : cell) * HSZ + kc + q * 8);
            cp16(dst, src, cell < 0 ? 0u : 16u);
        }
#pragma unroll
        for (int i = 0; i < 4; i++) {                     // B hi/lo: 512 chunks
            int c = tid + i * 128;
            int half = c >> 8;
            int rr = c & 255;
            int row = rr >> 2, q = rr & 3;
            uint32_t dst = stage + (half ? POFF_BL : POFF_BH) + row * PROWB + q * 16;
            const __nv_bfloat16* sp = (half ? g_WT_lo : g_WT_hi);
            cp16(dst, sp + ((size_t)(n0 + row) * HSZ + kc + q * 8), 16u);
        }
        cp_commit();
    };

    float acc[2][4][4];
#pragma unroll
    for (int mi = 0; mi < 2; mi++)
#pragma unroll
        for (int ni = 0; ni < 4; ni++)
#pragma unroll
            for (int q = 0; q < 4; q++) acc[mi][ni][q] = 0.f;

    int wm = wid & 1, wn = wid >> 1;       // 2 x 2 warp grid
    int laneRow = lane & 15;
    uint32_t lk = (uint32_t)(lane >> 4) * 16;
    uint32_t aRowOff = (uint32_t)(wm * 32 + laneRow) * PROWB + lk;
    uint32_t bRowOff = (uint32_t)(wn * 32 + laneRow) * PROWB + lk;

    const int KITER = 16;
    issue(0); issue(1);
    for (int kt = 0; kt < KITER; kt++) {
        if (kt + 1 < KITER) cp_wait<1>(); else cp_wait<0>();
        __syncthreads();
        if (kt + 2 < KITER) issue(kt + 2);
        gemm_chunk(sbase + (kt % NSTAGE) * PSTAGE, aRowOff, bRowOff, acc);
    }

    int qrow = lane >> 2, qcol = (lane & 3) * 2;
#pragma unroll
    for (int mi = 0; mi < 2; mi++) {
        int r0 = wm * 32 + mi * 16 + qrow;
        int c0 = rowCell[r0];
        int c1 = rowCell[r0 + 8];
#pragma unroll
        for (int ni = 0; ni < 4; ni++) {
            int col = n0 + wn * 32 + ni * 8 + qcol;
            if (c0 >= 0)
                *(float2*)(g_ACS + (size_t)c0 * NPROJ + col) =
                    make_float2(acc[mi][ni][0], acc[mi][ni][1]);
            if (c1 >= 0)
                *(float2*)(g_ACS + (size_t)c1 * NPROJ + col) =
                    make_float2(acc[mi][ni][2], acc[mi][ni][3]);
        }
    }
}

// ---------------------------------------------------------------------------
// Leaf GEMM via mma: g_ltmp = relu(x @ w_leaf + b). M=1536, N=512, K=1024.
// ---------------------------------------------------------------------------
__global__ __launch_bounds__(128, 3)
void leaf_mma(const float* __restrict__ bias) {
    extern __shared__ __align__(16) char dsm[];
    uint32_t sbase = smem_to_u32(dsm);
    int tid = threadIdx.x, wid = tid >> 5, lane = tid & 31;
    int n0 = blockIdx.x * 64;     // 8
    int m0 = blockIdx.y * 64;     // 24

    auto issue = [&](int s) {
        uint32_t stage = sbase + (s % NSTAGE) * PSTAGE;
        int kc = s * 32;
#pragma unroll
        for (int i = 0; i < 4; i++) {
            int c = tid + i * 128;
            int half = c >> 8;
            int rr = c & 255;
            int row = rr >> 2, q = rr & 3;
            uint32_t dst = stage + (half ? POFF_AL : POFF_AH) + row * PROWB + q * 16;
            const __nv_bfloat16* sp = (half ? g_Xl : g_Xh);
            cp16(dst, sp + ((size_t)(m0 + row) * 1024 + kc + q * 8), 16u);
        }
#pragma unroll
        for (int i = 0; i < 4; i++) {
            int c = tid + i * 128;
            int half = c >> 8;
            int rr = c & 255;
            int row = rr >> 2, q = rr & 3;
            uint32_t dst = stage + (half ? POFF_BL : POFF_BH) + row * PROWB + q * 16;
            const __nv_bfloat16* sp = (half ? g_WLl : g_WLh);
            cp16(dst, sp + ((size_t)(n0 + row) * 1024 + kc + q * 8), 16u);
        }
        cp_commit();
    };

    float acc[2][4][4];
#pragma unroll
    for (int mi = 0; mi < 2; mi++)
#pragma unroll
        for (int ni = 0; ni < 4; ni++)
#pragma unroll
            for (int q = 0; q < 4; q++) acc[mi][ni][q] = 0.f;

    int wm = wid & 1, wn = wid >> 1;
    int laneRow = lane & 15;
    uint32_t lk = (uint32_t)(lane >> 4) * 16;
    uint32_t aRowOff = (uint32_t)(wm * 32 + laneRow) * PROWB + lk;
    uint32_t bRowOff = (uint32_t)(wn * 32 + laneRow) * PROWB + lk;

    const int KITER = 32;
    issue(0); issue(1);
    for (int kt = 0; kt < KITER; kt++) {
        if (kt + 1 < KITER) cp_wait<1>(); else cp_wait<0>();
        __syncthreads();
        if (kt + 2 < KITER) issue(kt + 2);
        gemm_chunk(sbase + (kt % NSTAGE) * PSTAGE, aRowOff, bRowOff, acc);
    }

    int qrow = lane >> 2, qcol = (lane & 3) * 2;
#pragma unroll
    for (int mi = 0; mi < 2; mi++) {
        int r0 = m0 + wm * 32 + mi * 16 + qrow;
#pragma unroll
        for (int ni = 0; ni < 4; ni++) {
            int col = n0 + wn * 32 + ni * 8 + qcol;
            float2 bc = *(const float2*)&bias[col];
            *(float2*)(g_ltmp + (size_t)r0 * HSZ + col) =
                make_float2(fmaxf(acc[mi][ni][0] + bc.x, 0.f),
                            fmaxf(acc[mi][ni][1] + bc.y, 0.f));
            *(float2*)(g_ltmp + (size_t)(r0 + 8) * HSZ + col) =
                make_float2(fmaxf(acc[mi][ni][2] + bc.x, 0.f),
                            fmaxf(acc[mi][ni][3] + bc.y, 0.f));
        }
    }
}

// ---------------------------------------------------------------------------
// Normalize leaf rows -> chart cells (b, t) fp32 + bf16 hi/lo; zero leaf scores.
// ---------------------------------------------------------------------------
__global__ void leaf_norm(float* __restrict__ chart) {
    int r = blockIdx.x;
    int b = r >> 5, t = r & 31;
    int tid = threadIdx.x;            // 128
    const float4* src = (const float4*)(g_ltmp + (size_t)r * HSZ);
    float4 v = src[tid];
    float ss = v.x * v.x + v.y * v.y + v.z * v.z + v.w * v.w;
    __shared__ float red[4];
    __shared__ float s_inv;
    int w = tid >> 5, lane = tid & 31;
#pragma unroll
    for (int o = 16; o > 0; o >>= 1) ss += __shfl_xor_sync(0xffffffffu, ss, o);
    if (lane == 0) red[w] = ss;
    __syncthreads();
    if (tid == 0) {
        float tt = red[0] + red[1] + red[2] + red[3];
        s_inv = 1.f / fmaxf(sqrtf(tt), 1e-12f);
        g_sch[b * NCELL + t] = 0.f;
    }
    __syncthreads();
    float inv = s_inv;
    v.x *= inv; v.y *= inv; v.z *= inv; v.w *= inv;
    size_t base = ((size_t)b * NCELL + t) * HSZ;
    *(float4*)(chart + base + tid * 4) = v;
    float f[4] = {v.x, v.y, v.z, v.w};
    __align__(8) __nv_bfloat16 hi[4], lo[4];
#pragma unroll
    for (int i = 0; i < 4; i++) {
        hi[i] = __float2bfloat16(f[i]);
        lo[i] = __float2bfloat16(f[i] - __bfloat162float(hi[i]));
    }
    *(uint2*)(g_chh + base + tid * 4) = *(const uint2*)hi;
    *(uint2*)(g_chl + base + tid * 4) = *(const uint2*)lo;
}

// ---------------------------------------------------------------------------
// Combine: one block per output cell (b, pos) at `level`.
// ---------------------------------------------------------------------------
__global__ __launch_bounds__(256)
void combine_kernel(float* __restrict__ chart,
                    const float* __restrict__ b_comp,
                    int level) {
    int L = TLEN - level;
    int cidx = blockIdx.x;
    int b = cidx / L, pos = cidx - b * L;
    int cell = b * NCELL + offs(level) + pos;

    __shared__ float sv[32];
    __shared__ float pv[32];
    __shared__ float red[8];
    __shared__ float s_inv;

    int tid = threadIdx.x, w = tid >> 5, lane = tid & 31;

    // Pass 1: score per split (one warp per split, strided)
    for (int n = w; n < level; n += 8) {
        int lcell = b * NCELL + offs(n) + pos;
        int rcell = b * NCELL + offs(level - 1 - n) + pos + n + 1;
        const float4* Sh4 = (const float4*)(g_ACS + (size_t)lcell * NPROJ + 2 * HSZ);
        const float4* hr4 = (const float4*)(chart + (size_t)rcell * HSZ);
        float d = 0.f;
#pragma unroll 4
        for (int i = lane; i < HSZ / 4; i += 32) {
            float4 a = __ldg(Sh4 + i), c4 = __ldg(hr4 + i);
            d += a.x * c4.x + a.y * c4.y + a.z * c4.z + a.w * c4.w;
        }
#pragma unroll
        for (int o = 16; o > 0; o >>= 1) d += __shfl_xor_sync(0xffffffffu, d, o);
        if (lane == 0) sv[n] = d + g_sch[lcell] + g_sch[rcell];
    }
    __syncthreads();

    // Softmax + sbar (warp 0)
    if (w == 0) {
        float s = (lane < level) ? sv[lane] : -1e30f;
        float m = s;
#pragma unroll
        for (int o = 16; o > 0; o >>= 1) m = fmaxf(m, __shfl_xor_sync(0xffffffffu, m, o));
        float e = (lane < level) ? expf(s - m) : 0.f;
        float se = e;
#pragma unroll
        for (int o = 16; o > 0; o >>= 1) se += __shfl_xor_sync(0xffffffffu, se, o);
        float p = e / se;
        pv[lane] = p;
        float sp = (lane < level) ? s * p : 0.f;
#pragma unroll
        for (int o = 16; o > 0; o >>= 1) sp += __shfl_xor_sync(0xffffffffu, sp, o);
        if (lane == 0) g_sch[cell] = sp;
    }
    __syncthreads();

    // Pass 2: weighted relu-sum; each thread owns float2 at j = 2*tid.
    int j = tid * 2;
    const float2 bc = *(const float2*)&b_comp[j];
    float ax = 0.f, ay = 0.f;
    int base0 = b * NCELL + pos;
#pragma unroll 4
    for (int n = 0; n < level; n++) {
        int lcell = base0 + offs(n);
        int rcell = base0 + offs(level - 1 - n) + n + 1;
        float2 A = __ldg((const float2*)(g_ACS + (size_t)lcell * NPROJ + j));
        float2 C = __ldg((const float2*)(g_ACS + (size_t)rcell * NPROJ + HSZ + j));
        float p = pv[n];
        ax += p * fmaxf(A.x + C.x + bc.x, 0.f);
        ay += p * fmaxf(A.y + C.y + bc.y, 0.f);
    }

    // Normalize
    float ss = ax * ax + ay * ay;
#pragma unroll
    for (int o = 16; o > 0; o >>= 1) ss += __shfl_xor_sync(0xffffffffu, ss, o);
    if (lane == 0) red[w] = ss;
    __syncthreads();
    if (tid == 0) {
        float t = 0.f;
#pragma unroll
        for (int i = 0; i < 8; i++) t += red[i];
        s_inv = 1.f / fmaxf(sqrtf(t), 1e-12f);
    }
    __syncthreads();
    float inv = s_inv;
    float v0 = ax * inv, v1 = ay * inv;
    size_t base = (size_t)cell * HSZ;
    *(float2*)(chart + base + j) = make_float2(v0, v1);
    __nv_bfloat16 h0 = __float2bfloat16(v0);
    __nv_bfloat16 h1 = __float2bfloat16(v1);
    __align__(4) __nv_bfloat16 hv[2] = {h0, h1};
    __align__(4) __nv_bfloat16 lv[2] = {
        __float2bfloat16(v0 - __bfloat162float(h0)),
        __float2bfloat16(v1 - __bfloat162float(h1))};
    *(uint32_t*)(g_chh + base + j) = *(const uint32_t*)hv;
    *(uint32_t*)(g_chl + base + j) = *(const uint32_t*)lv;
}

// ---------------------------------------------------------------------------
extern "C" void kernel_launch(void* const* d_in, const int* in_sizes, int n_in,
                              void* d_out, int out_size) {
    const float* x      = (const float*)d_in[0];
    const float* w_leaf = (const float*)d_in[1];
    const float* b_leaf = (const float*)d_in[2];
    const float* w_comp = (const float*)d_in[3];
    const float* b_comp = (const float*)d_in[4];
    const float* s_bil  = (const float*)d_in[5];
    float* chart = (float*)d_out;

    (void)in_sizes; (void)n_in; (void)out_size;

    cudaFuncSetAttribute(proj_mma, cudaFuncAttributeMaxDynamicSharedMemorySize, DSMEM);
    cudaFuncSetAttribute(leaf_mma, cudaFuncAttributeMaxDynamicSharedMemorySize, DSMEM);

    pack_wt<<<(NPROJ * HSZ) / 256, 256>>>(w_comp, s_bil);
    pack_x<<<(BATCH * TLEN * 1024) / 256, 256>>>(x);
    pack_wl<<<(HSZ * 1024) / 256, 256>>>(w_leaf);

    leaf_mma<<<dim3(HSZ / 64, (BATCH * TLEN) / 64), 128, DSMEM>>>(b_leaf);
    leaf_norm<<<BATCH * TLEN, 128>>>(chart);
    proj_mma<<<dim3(NPROJ / 64, (BATCH * TLEN + 63) / 64), 128, DSMEM>>>(
        0, TLEN, BATCH * TLEN);

    for (int level = 1; level < TLEN; level++) {
        int L = TLEN - level;
        combine_kernel<<<BATCH * L, 256>>>(chart, b_comp, level);
        if (level < TLEN - 1) {
            int M = BATCH * L;
            proj_mma<<<dim3(NPROJ / 64, (M + 63) / 64), 128, DSMEM>>>(
                offs(level), L, M);
        }
    }
}